// round 1
// baseline (speedup 1.0000x reference)
#include <cuda_runtime.h>
#include <math.h>

#define B_   2
#define S_   2048
#define D_   2048
#define H_   16
#define HD_  128
#define LY_  512
#define DY_  2048
#define HHD  2048   // H*HD

// ---------------- scratch (no allocations allowed) ----------------
__device__ float g_q  [B_*S_*HHD];
__device__ float g_k  [B_*S_*HHD];
__device__ float g_v  [B_*S_*HHD];
__device__ float g_yk [B_*LY_*HHD];
__device__ float g_yv [B_*LY_*HHD];
__device__ float g_att[B_*S_*HHD];

// =====================================================================
// SGEMM: C[M,N] = A[M,K] @ B[K,N], all row-major. 128x128 tile, BK=8,
// 256 threads, 8x8 microtile. M%128==0, N%128==0, K%8==0 assumed.
// =====================================================================
__global__ void sgemm_kernel(const float* __restrict__ A,
                             const float* __restrict__ B,
                             float* __restrict__ C,
                             int M, int N, int K)
{
    const int BM = 128, BN = 128, BK = 8;
    __shared__ float As[BK][BM];
    __shared__ float Bs[BK][BN];

    int tid = threadIdx.x;
    int bm0 = blockIdx.y * BM;
    int bn0 = blockIdx.x * BN;
    int ty = tid >> 4;          // 0..15
    int tx = tid & 15;          // 0..15

    float acc[8][8];
#pragma unroll
    for (int i = 0; i < 8; i++)
#pragma unroll
        for (int j = 0; j < 8; j++) acc[i][j] = 0.f;

    int a_r = tid >> 1;           // 0..127
    int a_c = (tid & 1) * 4;      // 0 or 4
    int b_r = tid >> 5;           // 0..7
    int b_c = (tid & 31) * 4;     // 0..124

    const float* Ab = A + (size_t)bm0 * K;
    const float* Bb = B + bn0;

    for (int k0 = 0; k0 < K; k0 += BK) {
        float4 av = *(const float4*)(Ab + (size_t)a_r * K + k0 + a_c);
        float4 bv = *(const float4*)(Bb + (size_t)(k0 + b_r) * N + b_c);
        __syncthreads();
        As[a_c + 0][a_r] = av.x;
        As[a_c + 1][a_r] = av.y;
        As[a_c + 2][a_r] = av.z;
        As[a_c + 3][a_r] = av.w;
        *(float4*)&Bs[b_r][b_c] = bv;
        __syncthreads();
#pragma unroll
        for (int k = 0; k < BK; k++) {
            float ra[8], rb[8];
            *(float4*)(ra)     = *(const float4*)&As[k][ty * 8];
            *(float4*)(ra + 4) = *(const float4*)&As[k][ty * 8 + 4];
            *(float4*)(rb)     = *(const float4*)&Bs[k][tx * 8];
            *(float4*)(rb + 4) = *(const float4*)&Bs[k][tx * 8 + 4];
#pragma unroll
            for (int i = 0; i < 8; i++)
#pragma unroll
                for (int j = 0; j < 8; j++)
                    acc[i][j] = fmaf(ra[i], rb[j], acc[i][j]);
        }
    }

#pragma unroll
    for (int i = 0; i < 8; i++) {
        float* crow = C + (size_t)(bm0 + ty * 8 + i) * N + bn0 + tx * 8;
        float4 c0 = make_float4(acc[i][0], acc[i][1], acc[i][2], acc[i][3]);
        float4 c1 = make_float4(acc[i][4], acc[i][5], acc[i][6], acc[i][7]);
        *(float4*)(crow)     = c0;
        *(float4*)(crow + 4) = c1;
    }
}

// =====================================================================
// Fused LayerNorm (+optional RoPE, +output scale) over rows of width 2048.
// grid = #rows, 256 threads, 8 elems/thread (contiguous so RoPE pairs
// stay inside one thread).
// =====================================================================
__global__ void ln_rope_kernel(float* __restrict__ t,
                               const float* __restrict__ w,
                               const float* __restrict__ bias,
                               const float* __restrict__ freqs,
                               int Smod, float eps, float oscale, int do_rope)
{
    __shared__ float red[32];
    int row = blockIdx.x;
    int tid = threadIdx.x;
    float* p = t + (size_t)row * HHD;
    int base = tid * 8;

    float4 a = *(const float4*)(p + base);
    float4 c = *(const float4*)(p + base + 4);
    float v[8] = {a.x, a.y, a.z, a.w, c.x, c.y, c.z, c.w};

    float s1 = 0.f, s2 = 0.f;
#pragma unroll
    for (int j = 0; j < 8; j++) { s1 += v[j]; s2 += v[j] * v[j]; }
#pragma unroll
    for (int o = 16; o > 0; o >>= 1) {
        s1 += __shfl_down_sync(0xffffffffu, s1, o);
        s2 += __shfl_down_sync(0xffffffffu, s2, o);
    }
    int wid = tid >> 5, lane = tid & 31;
    if (lane == 0) { red[wid] = s1; red[8 + wid] = s2; }
    __syncthreads();
    if (tid == 0) {
        float t1 = 0.f, t2 = 0.f;
#pragma unroll
        for (int i = 0; i < 8; i++) { t1 += red[i]; t2 += red[8 + i]; }
        red[16] = t1; red[17] = t2;
    }
    __syncthreads();
    float mean = red[16] * (1.f / HHD);
    float var  = red[17] * (1.f / HHD) - mean * mean;
    float rstd = rsqrtf(fmaxf(var, 0.f) + eps);

#pragma unroll
    for (int j = 0; j < 8; j++) {
        int g = base + j;
        v[j] = (v[j] - mean) * rstd * w[g] + bias[g];
    }

    if (do_rope) {
        int s = row % Smod;
        const float* fr = freqs + (size_t)s * (HD_ / 2) * 2;  // [64][2]
#pragma unroll
        for (int jp = 0; jp < 4; jp++) {
            int g = base + 2 * jp;
            int pidx = (g & (HD_ - 1)) >> 1;
            float cs = fr[pidx * 2 + 0];
            float sn = fr[pidx * 2 + 1];
            float x0 = v[2 * jp], x1 = v[2 * jp + 1];
            v[2 * jp]     = x0 * cs - x1 * sn;
            v[2 * jp + 1] = x0 * sn + x1 * cs;
        }
    }
#pragma unroll
    for (int j = 0; j < 8; j++) v[j] *= oscale;

    *(float4*)(p + base)     = make_float4(v[0], v[1], v[2], v[3]);
    *(float4*)(p + base + 4) = make_float4(v[4], v[5], v[6], v[7]);
}

// =====================================================================
// Flash attention (fp32, masks all-true). One block per (qtile=64, h, b).
// K stored transposed in smem for conflict-free score GEMM; same buffer
// reused row-major for V in the PV stage. Online softmax (m,l,corr).
// If ACCUM: O += tanh(gate[h]) * attn  (cross-attention pass).
// =====================================================================
#define ABM 64
#define ABN 64
#define SP  68      // score row pitch
#define KTP 68      // transposed-K row pitch
#define KVBUF 8704  // max(128*KTP, ABM*HD_)
#define ATTN_SMEM_FLOATS (ABM*HD_ + KVBUF + ABM*SP + 3*ABM)

template <bool ACCUM>
__global__ void attn_kernel(const float* __restrict__ Qg,
                            const float* __restrict__ Kg,
                            const float* __restrict__ Vg,
                            float* __restrict__ Og,
                            const float* __restrict__ gate,
                            int Sq, int Sk)
{
    extern __shared__ float sm[];
    float* sQ  = sm;                    // [64][128]
    float* sKV = sQ + ABM * HD_;        // K^T [128][68] then V [64][128]
    float* sS  = sKV + KVBUF;           // [64][68]
    float* sM  = sS + ABM * SP;
    float* sL  = sM + ABM;
    float* sC  = sL + ABM;

    int tid = threadIdx.x;
    int qt = blockIdx.x, h = blockIdx.y, b = blockIdx.z;
    int s0 = qt * ABM;

    // load Q tile
    {
        int r  = tid >> 2;
        int d0 = (tid & 3) * 32;
        const float* qrow = Qg + ((size_t)(b * Sq + s0 + r) * HHD + h * HD_);
#pragma unroll
        for (int it = 0; it < 8; it++) {
            int d = d0 + it * 4;
            *(float4*)&sQ[r * HD_ + d] = *(const float4*)(qrow + d);
        }
    }
    if (tid < ABM) { sM[tid] = -1e30f; sL[tid] = 0.f; }

    int ty = tid >> 4, tx = tid & 15;
    int ar0 = ty * 4;       // output rows owned
    int ad0 = tx * 8;       // output dims owned
    int sc0 = tx * 4;       // score cols owned
    float acc[4][8];
#pragma unroll
    for (int i = 0; i < 4; i++)
#pragma unroll
        for (int j = 0; j < 8; j++) acc[i][j] = 0.f;

    __syncthreads();

    int nkt = Sk / ABN;
    for (int kt = 0; kt < nkt; kt++) {
        int k0 = kt * ABN;
        // ---- load K tile transposed: sKV[d*KTP + key]
        {
            int key = tid >> 2;
            int d0  = (tid & 3) * 32;
            const float* krow = Kg + ((size_t)(b * Sk + k0 + key) * HHD + h * HD_);
#pragma unroll
            for (int it = 0; it < 8; it++) {
                int d = d0 + it * 4;
                float4 vv = *(const float4*)(krow + d);
                sKV[(d + 0) * KTP + key] = vv.x;
                sKV[(d + 1) * KTP + key] = vv.y;
                sKV[(d + 2) * KTP + key] = vv.z;
                sKV[(d + 3) * KTP + key] = vv.w;
            }
        }
        __syncthreads();

        // ---- scores: 4 rows x 4 keys per thread
        float sc[4][4];
#pragma unroll
        for (int i = 0; i < 4; i++)
#pragma unroll
            for (int j = 0; j < 4; j++) sc[i][j] = 0.f;

#pragma unroll 8
        for (int kk = 0; kk < HD_; kk++) {
            float4 kb = *(const float4*)&sKV[kk * KTP + sc0];
            float q0 = sQ[(ar0 + 0) * HD_ + kk];
            float q1 = sQ[(ar0 + 1) * HD_ + kk];
            float q2 = sQ[(ar0 + 2) * HD_ + kk];
            float q3 = sQ[(ar0 + 3) * HD_ + kk];
            sc[0][0] = fmaf(q0, kb.x, sc[0][0]); sc[0][1] = fmaf(q0, kb.y, sc[0][1]);
            sc[0][2] = fmaf(q0, kb.z, sc[0][2]); sc[0][3] = fmaf(q0, kb.w, sc[0][3]);
            sc[1][0] = fmaf(q1, kb.x, sc[1][0]); sc[1][1] = fmaf(q1, kb.y, sc[1][1]);
            sc[1][2] = fmaf(q1, kb.z, sc[1][2]); sc[1][3] = fmaf(q1, kb.w, sc[1][3]);
            sc[2][0] = fmaf(q2, kb.x, sc[2][0]); sc[2][1] = fmaf(q2, kb.y, sc[2][1]);
            sc[2][2] = fmaf(q2, kb.z, sc[2][2]); sc[2][3] = fmaf(q2, kb.w, sc[2][3]);
            sc[3][0] = fmaf(q3, kb.x, sc[3][0]); sc[3][1] = fmaf(q3, kb.y, sc[3][1]);
            sc[3][2] = fmaf(q3, kb.z, sc[3][2]); sc[3][3] = fmaf(q3, kb.w, sc[3][3]);
        }
        __syncthreads();   // everyone done reading K tile

        // ---- spill scores to smem; load V tile (row-major) into sKV
#pragma unroll
        for (int i = 0; i < 4; i++) {
            *(float4*)&sS[(ar0 + i) * SP + sc0] =
                make_float4(sc[i][0], sc[i][1], sc[i][2], sc[i][3]);
        }
        {
            int vr = tid >> 2;
            int d0 = (tid & 3) * 32;
            const float* vrow = Vg + ((size_t)(b * Sk + k0 + vr) * HHD + h * HD_);
#pragma unroll
            for (int it = 0; it < 8; it++) {
                int d = d0 + it * 4;
                *(float4*)&sKV[vr * HD_ + d] = *(const float4*)(vrow + d);
            }
        }
        __syncthreads();

        // ---- online softmax (4 threads per row)
        {
            int rt = tid >> 2, qd = tid & 3;
            float* srow = &sS[rt * SP + qd * 16];
            float tmp[16];
            float mx = -1e30f;
#pragma unroll
            for (int c = 0; c < 16; c++) { tmp[c] = srow[c]; mx = fmaxf(mx, tmp[c]); }
            mx = fmaxf(mx, __shfl_xor_sync(0xffffffffu, mx, 1));
            mx = fmaxf(mx, __shfl_xor_sync(0xffffffffu, mx, 2));
            float mold = sM[rt];
            float mnew = fmaxf(mold, mx);
            float corr = __expf(mold - mnew);
            float lsum = 0.f;
#pragma unroll
            for (int c = 0; c < 16; c++) {
                float pe = __expf(tmp[c] - mnew);
                srow[c] = pe;
                lsum += pe;
            }
            lsum += __shfl_xor_sync(0xffffffffu, lsum, 1);
            lsum += __shfl_xor_sync(0xffffffffu, lsum, 2);
            if (qd == 0) {
                sM[rt] = mnew;
                sL[rt] = sL[rt] * corr + lsum;
                sC[rt] = corr;
            }
        }
        __syncthreads();

        // ---- rescale accumulators, then P @ V
#pragma unroll
        for (int i = 0; i < 4; i++) {
            float cf = sC[ar0 + i];
#pragma unroll
            for (int j = 0; j < 8; j++) acc[i][j] *= cf;
        }
#pragma unroll 4
        for (int j = 0; j < ABN; j++) {
            float4 v0 = *(const float4*)&sKV[j * HD_ + ad0];
            float4 v1 = *(const float4*)&sKV[j * HD_ + ad0 + 4];
            float p0 = sS[(ar0 + 0) * SP + j];
            float p1 = sS[(ar0 + 1) * SP + j];
            float p2 = sS[(ar0 + 2) * SP + j];
            float p3 = sS[(ar0 + 3) * SP + j];
            acc[0][0] = fmaf(p0, v0.x, acc[0][0]); acc[0][1] = fmaf(p0, v0.y, acc[0][1]);
            acc[0][2] = fmaf(p0, v0.z, acc[0][2]); acc[0][3] = fmaf(p0, v0.w, acc[0][3]);
            acc[0][4] = fmaf(p0, v1.x, acc[0][4]); acc[0][5] = fmaf(p0, v1.y, acc[0][5]);
            acc[0][6] = fmaf(p0, v1.z, acc[0][6]); acc[0][7] = fmaf(p0, v1.w, acc[0][7]);
            acc[1][0] = fmaf(p1, v0.x, acc[1][0]); acc[1][1] = fmaf(p1, v0.y, acc[1][1]);
            acc[1][2] = fmaf(p1, v0.z, acc[1][2]); acc[1][3] = fmaf(p1, v0.w, acc[1][3]);
            acc[1][4] = fmaf(p1, v1.x, acc[1][4]); acc[1][5] = fmaf(p1, v1.y, acc[1][5]);
            acc[1][6] = fmaf(p1, v1.z, acc[1][6]); acc[1][7] = fmaf(p1, v1.w, acc[1][7]);
            acc[2][0] = fmaf(p2, v0.x, acc[2][0]); acc[2][1] = fmaf(p2, v0.y, acc[2][1]);
            acc[2][2] = fmaf(p2, v0.z, acc[2][2]); acc[2][3] = fmaf(p2, v0.w, acc[2][3]);
            acc[2][4] = fmaf(p2, v1.x, acc[2][4]); acc[2][5] = fmaf(p2, v1.y, acc[2][5]);
            acc[2][6] = fmaf(p2, v1.z, acc[2][6]); acc[2][7] = fmaf(p2, v1.w, acc[2][7]);
            acc[3][0] = fmaf(p3, v0.x, acc[3][0]); acc[3][1] = fmaf(p3, v0.y, acc[3][1]);
            acc[3][2] = fmaf(p3, v0.z, acc[3][2]); acc[3][3] = fmaf(p3, v0.w, acc[3][3]);
            acc[3][4] = fmaf(p3, v1.x, acc[3][4]); acc[3][5] = fmaf(p3, v1.y, acc[3][5]);
            acc[3][6] = fmaf(p3, v1.z, acc[3][6]); acc[3][7] = fmaf(p3, v1.w, acc[3][7]);
        }
        __syncthreads();  // before next tile overwrites sKV / sS
    }

    // ---- epilogue
    float gt = 0.f;
    if (ACCUM) gt = tanhf(gate[h]);
#pragma unroll
    for (int i = 0; i < 4; i++) {
        float inv = 1.f / sL[ar0 + i];
        float* orow = Og + ((size_t)(b * Sq + s0 + ar0 + i) * HHD + h * HD_ + ad0);
        if (ACCUM) {
#pragma unroll
            for (int j = 0; j < 8; j++) orow[j] += gt * acc[i][j] * inv;
        } else {
#pragma unroll
            for (int j = 0; j < 8; j++) orow[j] = acc[i][j] * inv;
        }
    }
}

// =====================================================================
// launch
// =====================================================================
extern "C" void kernel_launch(void* const* d_in, const int* in_sizes, int n_in,
                              void* d_out, int out_size)
{
    const float* x     = (const float*)d_in[0];
    // d_in[1] x_mask: all true — unused
    const float* freqs = (const float*)d_in[2];
    const float* y     = (const float*)d_in[3];
    // d_in[4] y_mask: all true — unused
    const float* wq    = (const float*)d_in[5];
    const float* wk    = (const float*)d_in[6];
    const float* wv    = (const float*)d_in[7];
    const float* wo    = (const float*)d_in[8];
    const float* wky   = (const float*)d_in[9];
    const float* wvy   = (const float*)d_in[10];
    const float* gate  = (const float*)d_in[11];
    const float* qn_w  = (const float*)d_in[12];
    const float* qn_b  = (const float*)d_in[13];
    const float* kn_w  = (const float*)d_in[14];
    const float* kn_b  = (const float*)d_in[15];
    const float* kyn_w = (const float*)d_in[16];
    const float* kyn_b = (const float*)d_in[17];
    float* out = (float*)d_out;

    float *q, *k, *v, *yk, *yv, *att;
    cudaGetSymbolAddress((void**)&q,   g_q);
    cudaGetSymbolAddress((void**)&k,   g_k);
    cudaGetSymbolAddress((void**)&v,   g_v);
    cudaGetSymbolAddress((void**)&yk,  g_yk);
    cudaGetSymbolAddress((void**)&yv,  g_yv);
    cudaGetSymbolAddress((void**)&att, g_att);

    const int Mx = B_ * S_;    // 4096
    const int My = B_ * LY_;   // 1024

    dim3 gx(HHD / 128, Mx / 128);   // (16, 32)
    dim3 gy(HHD / 128, My / 128);   // (16, 8)

    // QKV + y projections
    sgemm_kernel<<<gx, 256>>>(x, wq, q, Mx, HHD, D_);
    sgemm_kernel<<<gx, 256>>>(x, wk, k, Mx, HHD, D_);
    sgemm_kernel<<<gx, 256>>>(x, wv, v, Mx, HHD, D_);
    sgemm_kernel<<<gy, 256>>>(y, wky, yk, My, HHD, DY_);
    sgemm_kernel<<<gy, 256>>>(y, wvy, yv, My, HHD, DY_);

    // LayerNorm (+RoPE). Attention scale folded into q.
    const float scale = 0.08838834764831845f;  // 1/sqrt(128)
    ln_rope_kernel<<<Mx, 256>>>(q,  qn_w,  qn_b,  freqs, S_, 1e-5f, scale, 1);
    ln_rope_kernel<<<Mx, 256>>>(k,  kn_w,  kn_b,  freqs, S_, 1e-5f, 1.f,   1);
    ln_rope_kernel<<<My, 256>>>(yk, kyn_w, kyn_b, freqs, 1,  1e-6f, 1.f,   0);

    // Attention: self writes, cross accumulates with tanh(gate)
    size_t smem = ATTN_SMEM_FLOATS * sizeof(float);
    cudaFuncSetAttribute(attn_kernel<false>,
                         cudaFuncAttributeMaxDynamicSharedMemorySize, (int)smem);
    cudaFuncSetAttribute(attn_kernel<true>,
                         cudaFuncAttributeMaxDynamicSharedMemorySize, (int)smem);
    attn_kernel<false><<<dim3(S_ / ABM, H_, B_), 256, smem>>>(q, k,  v,  att, nullptr, S_, S_);
    attn_kernel<true ><<<dim3(S_ / ABM, H_, B_), 256, smem>>>(q, yk, yv, att, gate,    S_, LY_);

    // Output projection
    sgemm_kernel<<<gx, 256>>>(att, wo, out, Mx, D_, HHD);
}

// round 4
// speedup vs baseline: 1.8202x; 1.8202x over previous
#include <cuda_runtime.h>
#include <cuda_bf16.h>
#include <math.h>
#include <stdint.h>

#define B_   2
#define S_   2048
#define D_   2048
#define H_   16
#define HD_  128
#define LY_  512
#define DY_  2048
#define HHD  2048   // H*HD

typedef __nv_bfloat16 bf16;

// ---------------- scratch (no allocations allowed) ----------------
__device__ float g_q  [B_*S_*HHD];
__device__ float g_k  [B_*S_*HHD];
__device__ float g_v  [B_*S_*HHD];
__device__ float g_yk [B_*LY_*HHD];
__device__ float g_yv [B_*LY_*HHD];
__device__ float g_att[B_*S_*HHD];
// hi/lo bf16 splits of activations
__device__ bf16 g_xh [B_*S_*D_];
__device__ bf16 g_xl [B_*S_*D_];
__device__ bf16 g_yh [B_*LY_*DY_];
__device__ bf16 g_yl [B_*LY_*DY_];
__device__ bf16 g_ath[B_*S_*HHD];
__device__ bf16 g_atl[B_*S_*HHD];
// transposed + hi/lo split weights [N][K] bf16
__device__ bf16 g_wqh [HHD*D_],  g_wql [HHD*D_];
__device__ bf16 g_wkh [HHD*D_],  g_wkl [HHD*D_];
__device__ bf16 g_wvh [HHD*D_],  g_wvl [HHD*D_];
__device__ bf16 g_woh [D_*HHD],  g_wol [D_*HHD];
__device__ bf16 g_wkyh[HHD*DY_], g_wkyl[HHD*DY_];
__device__ bf16 g_wvyh[HHD*DY_], g_wvyl[HHD*DY_];

// =====================================================================
// Generic helpers
// =====================================================================
__device__ __forceinline__ uint32_t smem_u32(const void* p) {
    uint32_t a;
    asm("{ .reg .u64 t; cvta.to.shared.u64 t, %1; cvt.u32.u64 %0, t; }"
        : "=r"(a) : "l"(p));
    return a;
}
#define MBARRIER_INIT(addr, cnt) \
    asm volatile("mbarrier.init.shared.b64 [%0], %1;" :: "r"(addr), "r"(cnt) : "memory")
#define MBARRIER_INVAL(addr) \
    asm volatile("mbarrier.inval.shared.b64 [%0];" :: "r"(addr) : "memory")

__device__ __forceinline__ void mbar_wait_parity(uint32_t mbar, uint32_t parity) {
    asm volatile(
        "{\n\t.reg .pred P1;\n\t"
        "WAIT_LOOP_%=:\n\t"
        "mbarrier.try_wait.parity.acquire.cta.shared::cta.b64 P1, [%0], %1, 0x989680;\n\t"
        "@P1 bra.uni WAIT_DONE_%=;\n\t"
        "bra.uni WAIT_LOOP_%=;\n\t"
        "WAIT_DONE_%=:\n\t}"
        :: "r"(mbar), "r"(parity) : "memory");
}

__device__ __forceinline__ uint32_t sw128(uint32_t off) {
    return off ^ ((off >> 3) & 0x70);
}

__device__ __forceinline__ void split_hl(float x, bf16& h, bf16& l) {
    h = __float2bfloat16_rn(x);
    l = __float2bfloat16_rn(x - __bfloat162float(h));
}

// =====================================================================
// tcgen05 helpers — arch-specific pass only
// =====================================================================
#if defined(__CUDA_ARCH_FEAT_SM103_ALL) || !defined(__CUDA_ARCH__)

__device__ __forceinline__ uint32_t elect_one() {
    uint32_t pred;
    asm volatile("{\n\t.reg .pred p;\n\telect.sync _|p, 0xFFFFFFFF;\n\t"
                 "selp.b32 %0, 1, 0, p;\n\t}" : "=r"(pred));
    return pred;
}
#define TCGEN05_ALLOC(smem_addr, ncols) \
    asm volatile("tcgen05.alloc.cta_group::1.sync.aligned.shared::cta.b32 [%0], %1;" \
                 :: "r"(smem_addr), "r"(ncols) : "memory")
#define TCGEN05_DEALLOC(tmem, ncols) \
    asm volatile("tcgen05.dealloc.cta_group::1.sync.aligned.b32 %0, %1;" :: "r"(tmem), "r"(ncols))
#define TCGEN05_RELINQ() \
    asm volatile("tcgen05.relinquish_alloc_permit.cta_group::1.sync.aligned;")
#define TCGEN05_COMMIT(mbar) \
    asm volatile("tcgen05.commit.cta_group::1.mbarrier::arrive::one.shared::cluster.b64 [%0];" \
                 :: "r"(mbar) : "memory")
#define TCGEN05_WAIT_LD() asm volatile("tcgen05.wait::ld.sync.aligned;" ::: "memory")
#define TCGEN05_FENCE_AFTER() asm volatile("tcgen05.fence::after_thread_sync;" ::: "memory")
#define FENCE_ASYNC_SHARED() asm volatile("fence.proxy.async.shared::cta;" ::: "memory")

#define TCGEN05_LD_X32(r, tmem_addr) \
    asm volatile( \
        "tcgen05.ld.sync.aligned.32x32b.x32.b32 " \
        "{%0, %1, %2, %3, %4, %5, %6, %7, " \
        " %8, %9, %10, %11, %12, %13, %14, %15, " \
        " %16, %17, %18, %19, %20, %21, %22, %23, " \
        " %24, %25, %26, %27, %28, %29, %30, %31}, [%32];" \
        : "=r"((r)[0]),  "=r"((r)[1]),  "=r"((r)[2]),  "=r"((r)[3]), \
          "=r"((r)[4]),  "=r"((r)[5]),  "=r"((r)[6]),  "=r"((r)[7]), \
          "=r"((r)[8]),  "=r"((r)[9]),  "=r"((r)[10]), "=r"((r)[11]), \
          "=r"((r)[12]), "=r"((r)[13]), "=r"((r)[14]), "=r"((r)[15]), \
          "=r"((r)[16]), "=r"((r)[17]), "=r"((r)[18]), "=r"((r)[19]), \
          "=r"((r)[20]), "=r"((r)[21]), "=r"((r)[22]), "=r"((r)[23]), \
          "=r"((r)[24]), "=r"((r)[25]), "=r"((r)[26]), "=r"((r)[27]), \
          "=r"((r)[28]), "=r"((r)[29]), "=r"((r)[30]), "=r"((r)[31]) \
        : "r"(tmem_addr))

// SW128 K-major smem descriptor: layout=SW128(2), version=1, SBO=64, LBO=1
__device__ __forceinline__ uint64_t make_desc_sw128(uint32_t addr) {
    uint64_t d = (uint64_t(2) << 61) | (uint64_t(1) << 46)
               | (uint64_t(64) << 32) | (uint64_t(1) << 16);
    return d | ((uint64_t)(addr >> 4) & 0x3FFF);
}

// bf16 SS MMA, cta_group::1
__device__ __forceinline__ void mma_bf16_ss(uint32_t d_tmem, uint64_t a_desc,
                                            uint64_t b_desc, uint32_t idesc,
                                            uint32_t enable) {
    asm volatile(
        "{\n\t.reg .pred p;\n\tsetp.ne.u32 p, %5, 0;\n\t"
        "tcgen05.mma.cta_group::1.kind::f16 [%0], %1, %2, %3, {%4, %4, %4, %4}, p;\n\t}"
        :: "r"(d_tmem), "l"(a_desc), "l"(b_desc), "r"(idesc), "r"(0u), "r"(enable)
        : "memory");
}
#endif

// =====================================================================
// bf16x3 GEMM: C[M,N] = (Ah+Al)[M,K] @ (Bh+Bl)^T, Bh/Bl are [N,K].
// C = Ah*Bh + Ah*Bl + Al*Bh in fp32 TMEM accumulator.
// Tile 128x256, BK=64 bf16 (=128B row), SW128, double-buffered.
// =====================================================================
#define GBM 128
#define GBN 256
#define GBK 64
#define STG_STRIDE 98304        // 96KB per stage
#define OFF_AH 0
#define OFF_AL 16384
#define OFF_BH 32768
#define OFF_BL 65536
#define GSMEM (1024 + 2*STG_STRIDE)   // 197632 bytes

// idesc: D=f32(1<<4), A=BF16(1<<7), B=BF16(1<<10), N=256, M=128
#define BF16_IDESC ((1u<<4) | (1u<<7) | (1u<<10) | ((GBN/8)<<17) | ((GBM/16)<<24))

__global__ void __launch_bounds__(256, 1) bf16x3_gemm_kernel(
    const bf16* __restrict__ Ah, const bf16* __restrict__ Al,
    const bf16* __restrict__ Bh, const bf16* __restrict__ Bl,
    float* __restrict__ C, int M, int N, int K)
{
#if defined(__CUDA_ARCH_FEAT_SM103_ALL) || !defined(__CUDA_ARCH__)
    extern __shared__ char smem[];
    uint32_t sb = smem_u32(smem);
    int tid = threadIdx.x, wid = tid >> 5, lane = tid & 31;
    int bm0 = blockIdx.y * GBM, bn0 = blockIdx.x * GBN;

    if (wid == 0) {
        TCGEN05_ALLOC(sb + 0, 256);
    }
    if (tid == 0) {
        MBARRIER_INIT(sb + 8, 1);
        MBARRIER_INIT(sb + 16, 1);
        MBARRIER_INIT(sb + 24, 1);
    }
    __syncthreads();
    uint32_t tmem;
    asm volatile("ld.shared.b32 %0, [%1];" : "=r"(tmem) : "r"(sb + 0));
    if (wid == 0) TCGEN05_RELINQ();

    int ph0 = 0, ph1 = 0;
    const int niter = K / GBK;

    for (int i = 0; i < niter; i++) {
        int s = i & 1;
        uint32_t stg = 1024 + s * STG_STRIDE;
        if (i >= 2) {
            if (s == 0) { mbar_wait_parity(sb + 8,  ph0); ph0 ^= 1; }
            else        { mbar_wait_parity(sb + 16, ph1); ph1 ^= 1; }
        }
        int k0 = i * GBK;
        // A hi/lo: 128 rows x 128B each (1024 x 16B chunks, 4/thread)
        {
#pragma unroll
            for (int r = 0; r < 4; r++) {
                int e = tid + r * 256;
                int row = e >> 3;
                int ch = e & 7;
                size_t goff = (size_t)(bm0 + row) * K + k0 + ch * 8;
                uint32_t soff = sw128((uint32_t)(row * 128 + ch * 16));
                *(uint4*)(smem + stg + OFF_AH + soff) = *(const uint4*)(Ah + goff);
                *(uint4*)(smem + stg + OFF_AL + soff) = *(const uint4*)(Al + goff);
            }
        }
        // B hi/lo: 256 rows x 128B each (2048 x 16B chunks, 8/thread)
        {
#pragma unroll
            for (int r = 0; r < 8; r++) {
                int e = tid + r * 256;
                int row = e >> 3;
                int ch = e & 7;
                size_t goff = (size_t)(bn0 + row) * K + k0 + ch * 8;
                uint32_t soff = sw128((uint32_t)(row * 128 + ch * 16));
                *(uint4*)(smem + stg + OFF_BH + soff) = *(const uint4*)(Bh + goff);
                *(uint4*)(smem + stg + OFF_BL + soff) = *(const uint4*)(Bl + goff);
            }
        }
        __syncthreads();

        if (wid == 0) {
            FENCE_ASYNC_SHARED();
            if (elect_one()) {
                uint64_t ah = make_desc_sw128(sb + stg + OFF_AH);
                uint64_t al = make_desc_sw128(sb + stg + OFF_AL);
                uint64_t bh = make_desc_sw128(sb + stg + OFF_BH);
                uint64_t bl = make_desc_sw128(sb + stg + OFF_BL);
                // 3 terms x 4 sub-K (K=16 bf16 = 32B = +2 desc units)
#pragma unroll
                for (int j = 0; j < 4; j++)
                    mma_bf16_ss(tmem, ah + j * 2, bh + j * 2, BF16_IDESC,
                                (i > 0 || j > 0) ? 1u : 0u);
#pragma unroll
                for (int j = 0; j < 4; j++)
                    mma_bf16_ss(tmem, ah + j * 2, bl + j * 2, BF16_IDESC, 1u);
#pragma unroll
                for (int j = 0; j < 4; j++)
                    mma_bf16_ss(tmem, al + j * 2, bh + j * 2, BF16_IDESC, 1u);
                TCGEN05_COMMIT(sb + 8 + 8 * s);
            }
        }
    }

    __syncthreads();
    if (wid == 0 && elect_one()) TCGEN05_COMMIT(sb + 24);
    mbar_wait_parity(sb + 24, 0);
    TCGEN05_FENCE_AFTER();

    // epilogue: warps 0-3 read their 32-lane subpartitions
    if (wid < 4) {
        float* crow = C + (size_t)(bm0 + wid * 32 + lane) * N + bn0;
#pragma unroll
        for (int c0 = 0; c0 < GBN; c0 += 32) {
            uint32_t r[32];
            TCGEN05_LD_X32(r, tmem + c0);
            TCGEN05_WAIT_LD();
#pragma unroll
            for (int j = 0; j < 32; j += 4) {
                *(float4*)(crow + c0 + j) = make_float4(
                    __uint_as_float(r[j]), __uint_as_float(r[j + 1]),
                    __uint_as_float(r[j + 2]), __uint_as_float(r[j + 3]));
            }
        }
    }
    __syncthreads();
    if (tid == 0) {
        MBARRIER_INVAL(sb + 8); MBARRIER_INVAL(sb + 16); MBARRIER_INVAL(sb + 24);
    }
    if (wid == 0) TCGEN05_DEALLOC(tmem, 256);

#else
    // -------------------- SIMT fallback (generic pass; not executed) ----
    extern __shared__ char smem_raw[];
    float* As = (float*)smem_raw;          // [8][128]
    float* Bs = As + 8 * 128;              // [8][128]

    int tid = threadIdx.x;
    int bm0 = blockIdx.y * GBM;
    int ty = tid >> 4, tx = tid & 15;
    int a_r = tid >> 1;
    int a_c = (tid & 1) * 4;

    for (int half = 0; half < 2; half++) {
        int bn0 = blockIdx.x * GBN + half * 128;
        float acc[8][8];
#pragma unroll
        for (int i = 0; i < 8; i++)
#pragma unroll
            for (int j = 0; j < 8; j++) acc[i][j] = 0.f;

        for (int k0 = 0; k0 < K; k0 += 8) {
            size_t ga = (size_t)(bm0 + a_r) * K + k0 + a_c;
            size_t gb = (size_t)(bn0 + a_r) * K + k0 + a_c;
            float av[4], bv[4];
#pragma unroll
            for (int j = 0; j < 4; j++) {
                av[j] = __bfloat162float(Ah[ga + j]) + __bfloat162float(Al[ga + j]);
                bv[j] = __bfloat162float(Bh[gb + j]) + __bfloat162float(Bl[gb + j]);
            }
            __syncthreads();
#pragma unroll
            for (int j = 0; j < 4; j++) {
                As[(a_c + j) * 128 + a_r] = av[j];
                Bs[(a_c + j) * 128 + a_r] = bv[j];
            }
            __syncthreads();
#pragma unroll
            for (int k = 0; k < 8; k++) {
                float ra[8], rb[8];
                *(float4*)(ra)     = *(const float4*)&As[k * 128 + ty * 8];
                *(float4*)(ra + 4) = *(const float4*)&As[k * 128 + ty * 8 + 4];
                *(float4*)(rb)     = *(const float4*)&Bs[k * 128 + tx * 8];
                *(float4*)(rb + 4) = *(const float4*)&Bs[k * 128 + tx * 8 + 4];
#pragma unroll
                for (int i = 0; i < 8; i++)
#pragma unroll
                    for (int j = 0; j < 8; j++)
                        acc[i][j] = fmaf(ra[i], rb[j], acc[i][j]);
            }
        }
        __syncthreads();
#pragma unroll
        for (int i = 0; i < 8; i++) {
            float* crow = C + (size_t)(bm0 + ty * 8 + i) * N + bn0 + tx * 8;
            *(float4*)(crow)     = make_float4(acc[i][0], acc[i][1], acc[i][2], acc[i][3]);
            *(float4*)(crow + 4) = make_float4(acc[i][4], acc[i][5], acc[i][6], acc[i][7]);
        }
    }
#endif
}

// =====================================================================
// elementwise fp32 -> bf16 hi/lo split
// =====================================================================
__global__ void split_kernel(const float* __restrict__ in,
                             bf16* __restrict__ hi, bf16* __restrict__ lo,
                             int n)
{
    int i = (blockIdx.x * blockDim.x + threadIdx.x) * 4;
    if (i >= n) return;
    float4 v = *(const float4*)(in + i);
    bf16 h0, l0, h1, l1, h2, l2, h3, l3;
    split_hl(v.x, h0, l0); split_hl(v.y, h1, l1);
    split_hl(v.z, h2, l2); split_hl(v.w, h3, l3);
    // pack 4 bf16 = 8 bytes
    uint2 hp, lp;
    ((bf16*)&hp)[0] = h0; ((bf16*)&hp)[1] = h1; ((bf16*)&hp)[2] = h2; ((bf16*)&hp)[3] = h3;
    ((bf16*)&lp)[0] = l0; ((bf16*)&lp)[1] = l1; ((bf16*)&lp)[2] = l2; ((bf16*)&lp)[3] = l3;
    *(uint2*)(hi + i) = hp;
    *(uint2*)(lo + i) = lp;
}

// =====================================================================
// 2048x2048 transpose + hi/lo split: in[K][N] fp32 -> out_hi/lo[N][K] bf16
// =====================================================================
__global__ void transpose_split_kernel(const float* __restrict__ in,
                                       bf16* __restrict__ oh,
                                       bf16* __restrict__ ol)
{
    __shared__ float t[32][33];
    int c0 = blockIdx.x * 32, r0 = blockIdx.y * 32;
    int tx = threadIdx.x, ty = threadIdx.y;
#pragma unroll
    for (int i = ty; i < 32; i += 8)
        t[i][tx] = in[(size_t)(r0 + i) * 2048 + c0 + tx];
    __syncthreads();
#pragma unroll
    for (int i = ty; i < 32; i += 8) {
        float x = t[tx][i];
        bf16 h, l;
        split_hl(x, h, l);
        size_t o = (size_t)(c0 + i) * 2048 + r0 + tx;
        oh[o] = h;
        ol[o] = l;
    }
}

// =====================================================================
// Fused LayerNorm (+optional RoPE, +output scale), rows of width 2048.
// =====================================================================
__global__ void ln_rope_kernel(float* __restrict__ t,
                               const float* __restrict__ w,
                               const float* __restrict__ bias,
                               const float* __restrict__ freqs,
                               int Smod, float eps, float oscale, int do_rope)
{
    __shared__ float red[32];
    int row = blockIdx.x;
    int tid = threadIdx.x;
    float* p = t + (size_t)row * HHD;
    int base = tid * 8;

    float4 a = *(const float4*)(p + base);
    float4 c = *(const float4*)(p + base + 4);
    float v[8] = {a.x, a.y, a.z, a.w, c.x, c.y, c.z, c.w};

    float s1 = 0.f, s2 = 0.f;
#pragma unroll
    for (int j = 0; j < 8; j++) { s1 += v[j]; s2 += v[j] * v[j]; }
#pragma unroll
    for (int o = 16; o > 0; o >>= 1) {
        s1 += __shfl_down_sync(0xffffffffu, s1, o);
        s2 += __shfl_down_sync(0xffffffffu, s2, o);
    }
    int wid = tid >> 5, lane = tid & 31;
    if (lane == 0) { red[wid] = s1; red[8 + wid] = s2; }
    __syncthreads();
    if (tid == 0) {
        float t1 = 0.f, t2 = 0.f;
#pragma unroll
        for (int i = 0; i < 8; i++) { t1 += red[i]; t2 += red[8 + i]; }
        red[16] = t1; red[17] = t2;
    }
    __syncthreads();
    float mean = red[16] * (1.f / HHD);
    float var  = red[17] * (1.f / HHD) - mean * mean;
    float rstd = rsqrtf(fmaxf(var, 0.f) + eps);

#pragma unroll
    for (int j = 0; j < 8; j++) {
        int g = base + j;
        v[j] = (v[j] - mean) * rstd * w[g] + bias[g];
    }

    if (do_rope) {
        int s = row % Smod;
        const float* fr = freqs + (size_t)s * (HD_ / 2) * 2;
#pragma unroll
        for (int jp = 0; jp < 4; jp++) {
            int g = base + 2 * jp;
            int pidx = (g & (HD_ - 1)) >> 1;
            float cs = fr[pidx * 2 + 0];
            float sn = fr[pidx * 2 + 1];
            float x0 = v[2 * jp], x1 = v[2 * jp + 1];
            v[2 * jp]     = x0 * cs - x1 * sn;
            v[2 * jp + 1] = x0 * sn + x1 * cs;
        }
    }
#pragma unroll
    for (int j = 0; j < 8; j++) v[j] *= oscale;

    *(float4*)(p + base)     = make_float4(v[0], v[1], v[2], v[3]);
    *(float4*)(p + base + 4) = make_float4(v[4], v[5], v[6], v[7]);
}

// =====================================================================
// Flash attention (fp32, masks all-true) — unchanged.
// =====================================================================
#define ABM 64
#define ABN 64
#define SP  68
#define KTP 68
#define KVBUF 8704
#define ATTN_SMEM_FLOATS (ABM*HD_ + KVBUF + ABM*SP + 3*ABM)

template <bool ACCUM>
__global__ void attn_kernel(const float* __restrict__ Qg,
                            const float* __restrict__ Kg,
                            const float* __restrict__ Vg,
                            float* __restrict__ Og,
                            const float* __restrict__ gate,
                            int Sq, int Sk)
{
    extern __shared__ float sm[];
    float* sQ  = sm;
    float* sKV = sQ + ABM * HD_;
    float* sS  = sKV + KVBUF;
    float* sM  = sS + ABM * SP;
    float* sL  = sM + ABM;
    float* sC  = sL + ABM;

    int tid = threadIdx.x;
    int qt = blockIdx.x, h = blockIdx.y, b = blockIdx.z;
    int s0 = qt * ABM;

    {
        int r  = tid >> 2;
        int d0 = (tid & 3) * 32;
        const float* qrow = Qg + ((size_t)(b * Sq + s0 + r) * HHD + h * HD_);
#pragma unroll
        for (int it = 0; it < 8; it++) {
            int d = d0 + it * 4;
            *(float4*)&sQ[r * HD_ + d] = *(const float4*)(qrow + d);
        }
    }
    if (tid < ABM) { sM[tid] = -1e30f; sL[tid] = 0.f; }

    int ty = tid >> 4, tx = tid & 15;
    int ar0 = ty * 4;
    int ad0 = tx * 8;
    int sc0 = tx * 4;
    float acc[4][8];
#pragma unroll
    for (int i = 0; i < 4; i++)
#pragma unroll
        for (int j = 0; j < 8; j++) acc[i][j] = 0.f;

    __syncthreads();

    int nkt = Sk / ABN;
    for (int kt = 0; kt < nkt; kt++) {
        int k0 = kt * ABN;
        {
            int key = tid >> 2;
            int d0  = (tid & 3) * 32;
            const float* krow = Kg + ((size_t)(b * Sk + k0 + key) * HHD + h * HD_);
#pragma unroll
            for (int it = 0; it < 8; it++) {
                int d = d0 + it * 4;
                float4 vv = *(const float4*)(krow + d);
                sKV[(d + 0) * KTP + key] = vv.x;
                sKV[(d + 1) * KTP + key] = vv.y;
                sKV[(d + 2) * KTP + key] = vv.z;
                sKV[(d + 3) * KTP + key] = vv.w;
            }
        }
        __syncthreads();

        float sc[4][4];
#pragma unroll
        for (int i = 0; i < 4; i++)
#pragma unroll
            for (int j = 0; j < 4; j++) sc[i][j] = 0.f;

#pragma unroll 8
        for (int kk = 0; kk < HD_; kk++) {
            float4 kb = *(const float4*)&sKV[kk * KTP + sc0];
            float q0 = sQ[(ar0 + 0) * HD_ + kk];
            float q1 = sQ[(ar0 + 1) * HD_ + kk];
            float q2 = sQ[(ar0 + 2) * HD_ + kk];
            float q3 = sQ[(ar0 + 3) * HD_ + kk];
            sc[0][0] = fmaf(q0, kb.x, sc[0][0]); sc[0][1] = fmaf(q0, kb.y, sc[0][1]);
            sc[0][2] = fmaf(q0, kb.z, sc[0][2]); sc[0][3] = fmaf(q0, kb.w, sc[0][3]);
            sc[1][0] = fmaf(q1, kb.x, sc[1][0]); sc[1][1] = fmaf(q1, kb.y, sc[1][1]);
            sc[1][2] = fmaf(q1, kb.z, sc[1][2]); sc[1][3] = fmaf(q1, kb.w, sc[1][3]);
            sc[2][0] = fmaf(q2, kb.x, sc[2][0]); sc[2][1] = fmaf(q2, kb.y, sc[2][1]);
            sc[2][2] = fmaf(q2, kb.z, sc[2][2]); sc[2][3] = fmaf(q2, kb.w, sc[2][3]);
            sc[3][0] = fmaf(q3, kb.x, sc[3][0]); sc[3][1] = fmaf(q3, kb.y, sc[3][1]);
            sc[3][2] = fmaf(q3, kb.z, sc[3][2]); sc[3][3] = fmaf(q3, kb.w, sc[3][3]);
        }
        __syncthreads();

#pragma unroll
        for (int i = 0; i < 4; i++) {
            *(float4*)&sS[(ar0 + i) * SP + sc0] =
                make_float4(sc[i][0], sc[i][1], sc[i][2], sc[i][3]);
        }
        {
            int vr = tid >> 2;
            int d0 = (tid & 3) * 32;
            const float* vrow = Vg + ((size_t)(b * Sk + k0 + vr) * HHD + h * HD_);
#pragma unroll
            for (int it = 0; it < 8; it++) {
                int d = d0 + it * 4;
                *(float4*)&sKV[vr * HD_ + d] = *(const float4*)(vrow + d);
            }
        }
        __syncthreads();

        {
            int rt = tid >> 2, qd = tid & 3;
            float* srow = &sS[rt * SP + qd * 16];
            float tmp[16];
            float mx = -1e30f;
#pragma unroll
            for (int c = 0; c < 16; c++) { tmp[c] = srow[c]; mx = fmaxf(mx, tmp[c]); }
            mx = fmaxf(mx, __shfl_xor_sync(0xffffffffu, mx, 1));
            mx = fmaxf(mx, __shfl_xor_sync(0xffffffffu, mx, 2));
            float mold = sM[rt];
            float mnew = fmaxf(mold, mx);
            float corr = __expf(mold - mnew);
            float lsum = 0.f;
#pragma unroll
            for (int c = 0; c < 16; c++) {
                float pe = __expf(tmp[c] - mnew);
                srow[c] = pe;
                lsum += pe;
            }
            lsum += __shfl_xor_sync(0xffffffffu, lsum, 1);
            lsum += __shfl_xor_sync(0xffffffffu, lsum, 2);
            if (qd == 0) {
                sM[rt] = mnew;
                sL[rt] = sL[rt] * corr + lsum;
                sC[rt] = corr;
            }
        }
        __syncthreads();

#pragma unroll
        for (int i = 0; i < 4; i++) {
            float cf = sC[ar0 + i];
#pragma unroll
            for (int j = 0; j < 8; j++) acc[i][j] *= cf;
        }
#pragma unroll 4
        for (int j = 0; j < ABN; j++) {
            float4 v0 = *(const float4*)&sKV[j * HD_ + ad0];
            float4 v1 = *(const float4*)&sKV[j * HD_ + ad0 + 4];
            float p0 = sS[(ar0 + 0) * SP + j];
            float p1 = sS[(ar0 + 1) * SP + j];
            float p2 = sS[(ar0 + 2) * SP + j];
            float p3 = sS[(ar0 + 3) * SP + j];
            acc[0][0] = fmaf(p0, v0.x, acc[0][0]); acc[0][1] = fmaf(p0, v0.y, acc[0][1]);
            acc[0][2] = fmaf(p0, v0.z, acc[0][2]); acc[0][3] = fmaf(p0, v0.w, acc[0][3]);
            acc[0][4] = fmaf(p0, v1.x, acc[0][4]); acc[0][5] = fmaf(p0, v1.y, acc[0][5]);
            acc[0][6] = fmaf(p0, v1.z, acc[0][6]); acc[0][7] = fmaf(p0, v1.w, acc[0][7]);
            acc[1][0] = fmaf(p1, v0.x, acc[1][0]); acc[1][1] = fmaf(p1, v0.y, acc[1][1]);
            acc[1][2] = fmaf(p1, v0.z, acc[1][2]); acc[1][3] = fmaf(p1, v0.w, acc[1][3]);
            acc[1][4] = fmaf(p1, v1.x, acc[1][4]); acc[1][5] = fmaf(p1, v1.y, acc[1][5]);
            acc[1][6] = fmaf(p1, v1.z, acc[1][6]); acc[1][7] = fmaf(p1, v1.w, acc[1][7]);
            acc[2][0] = fmaf(p2, v0.x, acc[2][0]); acc[2][1] = fmaf(p2, v0.y, acc[2][1]);
            acc[2][2] = fmaf(p2, v0.z, acc[2][2]); acc[2][3] = fmaf(p2, v0.w, acc[2][3]);
            acc[2][4] = fmaf(p2, v1.x, acc[2][4]); acc[2][5] = fmaf(p2, v1.y, acc[2][5]);
            acc[2][6] = fmaf(p2, v1.z, acc[2][6]); acc[2][7] = fmaf(p2, v1.w, acc[2][7]);
            acc[3][0] = fmaf(p3, v0.x, acc[3][0]); acc[3][1] = fmaf(p3, v0.y, acc[3][1]);
            acc[3][2] = fmaf(p3, v0.z, acc[3][2]); acc[3][3] = fmaf(p3, v0.w, acc[3][3]);
            acc[3][4] = fmaf(p3, v1.x, acc[3][4]); acc[3][5] = fmaf(p3, v1.y, acc[3][5]);
            acc[3][6] = fmaf(p3, v1.z, acc[3][6]); acc[3][7] = fmaf(p3, v1.w, acc[3][7]);
        }
        __syncthreads();
    }

    float gt = 0.f;
    if (ACCUM) gt = tanhf(gate[h]);
#pragma unroll
    for (int i = 0; i < 4; i++) {
        float inv = 1.f / sL[ar0 + i];
        float* orow = Og + ((size_t)(b * Sq + s0 + ar0 + i) * HHD + h * HD_ + ad0);
        if (ACCUM) {
#pragma unroll
            for (int j = 0; j < 8; j++) orow[j] += gt * acc[i][j] * inv;
        } else {
#pragma unroll
            for (int j = 0; j < 8; j++) orow[j] = acc[i][j] * inv;
        }
    }
}

// =====================================================================
// launch
// =====================================================================
extern "C" void kernel_launch(void* const* d_in, const int* in_sizes, int n_in,
                              void* d_out, int out_size)
{
    const float* x     = (const float*)d_in[0];
    const float* freqs = (const float*)d_in[2];
    const float* y     = (const float*)d_in[3];
    const float* wq    = (const float*)d_in[5];
    const float* wk    = (const float*)d_in[6];
    const float* wv    = (const float*)d_in[7];
    const float* wo    = (const float*)d_in[8];
    const float* wky   = (const float*)d_in[9];
    const float* wvy   = (const float*)d_in[10];
    const float* gate  = (const float*)d_in[11];
    const float* qn_w  = (const float*)d_in[12];
    const float* qn_b  = (const float*)d_in[13];
    const float* kn_w  = (const float*)d_in[14];
    const float* kn_b  = (const float*)d_in[15];
    const float* kyn_w = (const float*)d_in[16];
    const float* kyn_b = (const float*)d_in[17];
    float* out = (float*)d_out;

    float *q, *k, *v, *yk, *yv, *att;
    bf16 *xh, *xl, *yh, *yl, *ath, *atl;
    bf16 *wqh, *wql, *wkh, *wkl, *wvh, *wvl, *woh, *wol, *wkyh, *wkyl, *wvyh, *wvyl;
    cudaGetSymbolAddress((void**)&q,    g_q);
    cudaGetSymbolAddress((void**)&k,    g_k);
    cudaGetSymbolAddress((void**)&v,    g_v);
    cudaGetSymbolAddress((void**)&yk,   g_yk);
    cudaGetSymbolAddress((void**)&yv,   g_yv);
    cudaGetSymbolAddress((void**)&att,  g_att);
    cudaGetSymbolAddress((void**)&xh,   g_xh);
    cudaGetSymbolAddress((void**)&xl,   g_xl);
    cudaGetSymbolAddress((void**)&yh,   g_yh);
    cudaGetSymbolAddress((void**)&yl,   g_yl);
    cudaGetSymbolAddress((void**)&ath,  g_ath);
    cudaGetSymbolAddress((void**)&atl,  g_atl);
    cudaGetSymbolAddress((void**)&wqh,  g_wqh);  cudaGetSymbolAddress((void**)&wql,  g_wql);
    cudaGetSymbolAddress((void**)&wkh,  g_wkh);  cudaGetSymbolAddress((void**)&wkl,  g_wkl);
    cudaGetSymbolAddress((void**)&wvh,  g_wvh);  cudaGetSymbolAddress((void**)&wvl,  g_wvl);
    cudaGetSymbolAddress((void**)&woh,  g_woh);  cudaGetSymbolAddress((void**)&wol,  g_wol);
    cudaGetSymbolAddress((void**)&wkyh, g_wkyh); cudaGetSymbolAddress((void**)&wkyl, g_wkyl);
    cudaGetSymbolAddress((void**)&wvyh, g_wvyh); cudaGetSymbolAddress((void**)&wvyl, g_wvyl);

    const int Mx = B_ * S_;    // 4096
    const int My = B_ * LY_;   // 1024

    // weights: transpose + split [K,N] -> [N,K] bf16 hi/lo
    dim3 tg(64, 64), tb(32, 8);
    transpose_split_kernel<<<tg, tb>>>(wq,  wqh,  wql);
    transpose_split_kernel<<<tg, tb>>>(wk,  wkh,  wkl);
    transpose_split_kernel<<<tg, tb>>>(wv,  wvh,  wvl);
    transpose_split_kernel<<<tg, tb>>>(wo,  woh,  wol);
    transpose_split_kernel<<<tg, tb>>>(wky, wkyh, wkyl);
    transpose_split_kernel<<<tg, tb>>>(wvy, wvyh, wvyl);

    // activations split
    split_kernel<<<(Mx * D_ / 4 + 255) / 256, 256>>>(x, xh, xl, Mx * D_);
    split_kernel<<<(My * DY_ / 4 + 255) / 256, 256>>>(y, yh, yl, My * DY_);

    // tcgen05 bf16x3 GEMMs
    cudaFuncSetAttribute(bf16x3_gemm_kernel,
                         cudaFuncAttributeMaxDynamicSharedMemorySize, GSMEM);
    dim3 gx(HHD / GBN, Mx / GBM);   // (8, 32)
    dim3 gy(HHD / GBN, My / GBM);   // (8, 8)
    bf16x3_gemm_kernel<<<gx, 256, GSMEM>>>(xh, xl, wqh,  wql,  q,  Mx, HHD, D_);
    bf16x3_gemm_kernel<<<gx, 256, GSMEM>>>(xh, xl, wkh,  wkl,  k,  Mx, HHD, D_);
    bf16x3_gemm_kernel<<<gx, 256, GSMEM>>>(xh, xl, wvh,  wvl,  v,  Mx, HHD, D_);
    bf16x3_gemm_kernel<<<gy, 256, GSMEM>>>(yh, yl, wkyh, wkyl, yk, My, HHD, DY_);
    bf16x3_gemm_kernel<<<gy, 256, GSMEM>>>(yh, yl, wvyh, wvyl, yv, My, HHD, DY_);

    // LayerNorm (+RoPE). Attention scale folded into q.
    const float scale = 0.08838834764831845f;  // 1/sqrt(128)
    ln_rope_kernel<<<Mx, 256>>>(q,  qn_w,  qn_b,  freqs, S_, 1e-5f, scale, 1);
    ln_rope_kernel<<<Mx, 256>>>(k,  kn_w,  kn_b,  freqs, S_, 1e-5f, 1.f,   1);
    ln_rope_kernel<<<My, 256>>>(yk, kyn_w, kyn_b, freqs, 1,  1e-6f, 1.f,   0);

    // Attention: self writes, cross accumulates with tanh(gate)
    size_t smem = ATTN_SMEM_FLOATS * sizeof(float);
    cudaFuncSetAttribute(attn_kernel<false>,
                         cudaFuncAttributeMaxDynamicSharedMemorySize, (int)smem);
    cudaFuncSetAttribute(attn_kernel<true>,
                         cudaFuncAttributeMaxDynamicSharedMemorySize, (int)smem);
    attn_kernel<false><<<dim3(S_ / ABM, H_, B_), 256, smem>>>(q, k,  v,  att, nullptr, S_, S_);
    attn_kernel<true ><<<dim3(S_ / ABM, H_, B_), 256, smem>>>(q, yk, yv, att, gate,    S_, LY_);

    // Output projection: split att then tensor-core GEMM
    split_kernel<<<(Mx * HHD / 4 + 255) / 256, 256>>>(att, ath, atl, Mx * HHD);
    bf16x3_gemm_kernel<<<dim3(D_ / GBN, Mx / GBM), 256, GSMEM>>>(
        ath, atl, woh, wol, out, Mx, D_, HHD);
}

// round 7
// speedup vs baseline: 4.2433x; 2.3313x over previous
#include <cuda_runtime.h>
#include <cuda_bf16.h>
#include <math.h>
#include <stdint.h>

#define B_   2
#define S_   2048
#define D_   2048
#define H_   16
#define HD_  128
#define LY_  512
#define DY_  2048
#define HHD  2048   // H*HD

typedef __nv_bfloat16 bf16;

// ---------------- scratch (no allocations allowed) ----------------
__device__ float g_q  [B_*S_*HHD];
__device__ float g_k  [B_*S_*HHD];
__device__ float g_v  [B_*S_*HHD];
__device__ float g_yk [B_*LY_*HHD];
__device__ float g_yv [B_*LY_*HHD];
// hi/lo bf16 splits of activations
__device__ bf16 g_xh [B_*S_*D_];
__device__ bf16 g_xl [B_*S_*D_];
__device__ bf16 g_yh [B_*LY_*DY_];
__device__ bf16 g_yl [B_*LY_*DY_];
__device__ bf16 g_ath[B_*S_*HHD];
__device__ bf16 g_atl[B_*S_*HHD];
// transposed + hi/lo split weights [N][K] bf16
__device__ bf16 g_wqh [HHD*D_],  g_wql [HHD*D_];
__device__ bf16 g_wkh [HHD*D_],  g_wkl [HHD*D_];
__device__ bf16 g_wvh [HHD*D_],  g_wvl [HHD*D_];
__device__ bf16 g_woh [D_*HHD],  g_wol [D_*HHD];
__device__ bf16 g_wkyh[HHD*DY_], g_wkyl[HHD*DY_];
__device__ bf16 g_wvyh[HHD*DY_], g_wvyl[HHD*DY_];

// =====================================================================
// Generic helpers
// =====================================================================
__device__ __forceinline__ uint32_t smem_u32(const void* p) {
    uint32_t a;
    asm("{ .reg .u64 t; cvta.to.shared.u64 t, %1; cvt.u32.u64 %0, t; }"
        : "=r"(a) : "l"(p));
    return a;
}
#define MBARRIER_INIT(addr, cnt) \
    asm volatile("mbarrier.init.shared.b64 [%0], %1;" :: "r"(addr), "r"(cnt) : "memory")
#define MBARRIER_INVAL(addr) \
    asm volatile("mbarrier.inval.shared.b64 [%0];" :: "r"(addr) : "memory")

__device__ __forceinline__ void mbar_wait_parity(uint32_t mbar, uint32_t parity) {
    asm volatile(
        "{\n\t.reg .pred P1;\n\t"
        "WAIT_LOOP_%=:\n\t"
        "mbarrier.try_wait.parity.acquire.cta.shared::cta.b64 P1, [%0], %1, 0x989680;\n\t"
        "@P1 bra.uni WAIT_DONE_%=;\n\t"
        "bra.uni WAIT_LOOP_%=;\n\t"
        "WAIT_DONE_%=:\n\t}"
        :: "r"(mbar), "r"(parity) : "memory");
}

__device__ __forceinline__ uint32_t sw128(uint32_t off) {
    return off ^ ((off >> 3) & 0x70);
}

__device__ __forceinline__ void split_hl(float x, bf16& h, bf16& l) {
    h = __float2bfloat16_rn(x);
    l = __float2bfloat16_rn(x - __bfloat162float(h));
}

__device__ __forceinline__ uint32_t pack2(float lo, float hi) {
    __nv_bfloat162 t = __floats2bfloat162_rn(lo, hi);   // .x = lo half
    return *(uint32_t*)&t;
}

// =====================================================================
// tcgen05 helpers — arch-specific pass only
// =====================================================================
#if defined(__CUDA_ARCH_FEAT_SM103_ALL) || !defined(__CUDA_ARCH__)

__device__ __forceinline__ uint32_t elect_one() {
    uint32_t pred;
    asm volatile("{\n\t.reg .pred p;\n\telect.sync _|p, 0xFFFFFFFF;\n\t"
                 "selp.b32 %0, 1, 0, p;\n\t}" : "=r"(pred));
    return pred;
}
#define TCGEN05_ALLOC(smem_addr, ncols) \
    asm volatile("tcgen05.alloc.cta_group::1.sync.aligned.shared::cta.b32 [%0], %1;" \
                 :: "r"(smem_addr), "r"(ncols) : "memory")
#define TCGEN05_DEALLOC(tmem, ncols) \
    asm volatile("tcgen05.dealloc.cta_group::1.sync.aligned.b32 %0, %1;" :: "r"(tmem), "r"(ncols))
#define TCGEN05_RELINQ() \
    asm volatile("tcgen05.relinquish_alloc_permit.cta_group::1.sync.aligned;")
#define TCGEN05_COMMIT(mbar) \
    asm volatile("tcgen05.commit.cta_group::1.mbarrier::arrive::one.shared::cluster.b64 [%0];" \
                 :: "r"(mbar) : "memory")
#define TCGEN05_WAIT_LD() asm volatile("tcgen05.wait::ld.sync.aligned;" ::: "memory")
#define TCGEN05_FENCE_BEFORE() asm volatile("tcgen05.fence::before_thread_sync;" ::: "memory")
#define TCGEN05_FENCE_AFTER()  asm volatile("tcgen05.fence::after_thread_sync;" ::: "memory")
#define FENCE_ASYNC_SHARED() asm volatile("fence.proxy.async.shared::cta;" ::: "memory")

#define TCGEN05_LD_X32(r, tmem_addr) \
    asm volatile( \
        "tcgen05.ld.sync.aligned.32x32b.x32.b32 " \
        "{%0, %1, %2, %3, %4, %5, %6, %7, " \
        " %8, %9, %10, %11, %12, %13, %14, %15, " \
        " %16, %17, %18, %19, %20, %21, %22, %23, " \
        " %24, %25, %26, %27, %28, %29, %30, %31}, [%32];" \
        : "=r"((r)[0]),  "=r"((r)[1]),  "=r"((r)[2]),  "=r"((r)[3]), \
          "=r"((r)[4]),  "=r"((r)[5]),  "=r"((r)[6]),  "=r"((r)[7]), \
          "=r"((r)[8]),  "=r"((r)[9]),  "=r"((r)[10]), "=r"((r)[11]), \
          "=r"((r)[12]), "=r"((r)[13]), "=r"((r)[14]), "=r"((r)[15]), \
          "=r"((r)[16]), "=r"((r)[17]), "=r"((r)[18]), "=r"((r)[19]), \
          "=r"((r)[20]), "=r"((r)[21]), "=r"((r)[22]), "=r"((r)[23]), \
          "=r"((r)[24]), "=r"((r)[25]), "=r"((r)[26]), "=r"((r)[27]), \
          "=r"((r)[28]), "=r"((r)[29]), "=r"((r)[30]), "=r"((r)[31]) \
        : "r"(tmem_addr))

// SW128 K-major smem descriptor: layout=SW128(2), version=1, SBO=64, LBO=1
__device__ __forceinline__ uint64_t make_desc_sw128(uint32_t addr) {
    uint64_t d = (uint64_t(2) << 61) | (uint64_t(1) << 46)
               | (uint64_t(64) << 32) | (uint64_t(1) << 16);
    return d | ((uint64_t)(addr >> 4) & 0x3FFF);
}

// bf16 SS MMA
__device__ __forceinline__ void mma_bf16_ss(uint32_t d_tmem, uint64_t a_desc,
                                            uint64_t b_desc, uint32_t idesc,
                                            uint32_t enable) {
    asm volatile(
        "{\n\t.reg .pred p;\n\tsetp.ne.u32 p, %5, 0;\n\t"
        "tcgen05.mma.cta_group::1.kind::f16 [%0], %1, %2, %3, {%4, %4, %4, %4}, p;\n\t}"
        :: "r"(d_tmem), "l"(a_desc), "l"(b_desc), "r"(idesc), "r"(0u), "r"(enable)
        : "memory");
}
#endif

// =====================================================================
// bf16x3 GEMM (validated in R4): C = (Ah+Al) @ (Bh+Bl)^T
// =====================================================================
#define GBM 128
#define GBN 256
#define GBK 64
#define STG_STRIDE 98304
#define OFF_AH 0
#define OFF_AL 16384
#define OFF_BH 32768
#define OFF_BL 65536
#define GSMEM (1024 + 2*STG_STRIDE)

#define BF16_IDESC ((1u<<4) | (1u<<7) | (1u<<10) | ((GBN/8)<<17) | ((GBM/16)<<24))

__global__ void __launch_bounds__(256, 1) bf16x3_gemm_kernel(
    const bf16* __restrict__ Ah, const bf16* __restrict__ Al,
    const bf16* __restrict__ Bh, const bf16* __restrict__ Bl,
    float* __restrict__ C, int M, int N, int K)
{
#if defined(__CUDA_ARCH_FEAT_SM103_ALL) || !defined(__CUDA_ARCH__)
    extern __shared__ char smem[];
    uint32_t sb = smem_u32(smem);
    int tid = threadIdx.x, wid = tid >> 5, lane = tid & 31;
    int bm0 = blockIdx.y * GBM, bn0 = blockIdx.x * GBN;

    if (wid == 0) TCGEN05_ALLOC(sb + 0, 256);
    if (tid == 0) {
        MBARRIER_INIT(sb + 8, 1);
        MBARRIER_INIT(sb + 16, 1);
        MBARRIER_INIT(sb + 24, 1);
    }
    __syncthreads();
    uint32_t tmem;
    asm volatile("ld.shared.b32 %0, [%1];" : "=r"(tmem) : "r"(sb + 0));
    if (wid == 0) TCGEN05_RELINQ();

    int ph0 = 0, ph1 = 0;
    const int niter = K / GBK;

    for (int i = 0; i < niter; i++) {
        int s = i & 1;
        uint32_t stg = 1024 + s * STG_STRIDE;
        if (i >= 2) {
            if (s == 0) { mbar_wait_parity(sb + 8,  ph0); ph0 ^= 1; }
            else        { mbar_wait_parity(sb + 16, ph1); ph1 ^= 1; }
        }
        int k0 = i * GBK;
        {
#pragma unroll
            for (int r = 0; r < 4; r++) {
                int e = tid + r * 256;
                int row = e >> 3;
                int ch = e & 7;
                size_t goff = (size_t)(bm0 + row) * K + k0 + ch * 8;
                uint32_t soff = sw128((uint32_t)(row * 128 + ch * 16));
                *(uint4*)(smem + stg + OFF_AH + soff) = *(const uint4*)(Ah + goff);
                *(uint4*)(smem + stg + OFF_AL + soff) = *(const uint4*)(Al + goff);
            }
        }
        {
#pragma unroll
            for (int r = 0; r < 8; r++) {
                int e = tid + r * 256;
                int row = e >> 3;
                int ch = e & 7;
                size_t goff = (size_t)(bn0 + row) * K + k0 + ch * 8;
                uint32_t soff = sw128((uint32_t)(row * 128 + ch * 16));
                *(uint4*)(smem + stg + OFF_BH + soff) = *(const uint4*)(Bh + goff);
                *(uint4*)(smem + stg + OFF_BL + soff) = *(const uint4*)(Bl + goff);
            }
        }
        __syncthreads();

        if (wid == 0) {
            FENCE_ASYNC_SHARED();
            if (elect_one()) {
                uint64_t ah = make_desc_sw128(sb + stg + OFF_AH);
                uint64_t al = make_desc_sw128(sb + stg + OFF_AL);
                uint64_t bh = make_desc_sw128(sb + stg + OFF_BH);
                uint64_t bl = make_desc_sw128(sb + stg + OFF_BL);
#pragma unroll
                for (int j = 0; j < 4; j++)
                    mma_bf16_ss(tmem, ah + j * 2, bh + j * 2, BF16_IDESC,
                                (i > 0 || j > 0) ? 1u : 0u);
#pragma unroll
                for (int j = 0; j < 4; j++)
                    mma_bf16_ss(tmem, ah + j * 2, bl + j * 2, BF16_IDESC, 1u);
#pragma unroll
                for (int j = 0; j < 4; j++)
                    mma_bf16_ss(tmem, al + j * 2, bh + j * 2, BF16_IDESC, 1u);
                TCGEN05_COMMIT(sb + 8 + 8 * s);
            }
        }
    }

    __syncthreads();
    if (wid == 0 && elect_one()) TCGEN05_COMMIT(sb + 24);
    mbar_wait_parity(sb + 24, 0);
    TCGEN05_FENCE_AFTER();

    if (wid < 4) {
        float* crow = C + (size_t)(bm0 + wid * 32 + lane) * N + bn0;
#pragma unroll
        for (int c0 = 0; c0 < GBN; c0 += 32) {
            uint32_t r[32];
            TCGEN05_LD_X32(r, tmem + c0);
            TCGEN05_WAIT_LD();
#pragma unroll
            for (int j = 0; j < 32; j += 4) {
                *(float4*)(crow + c0 + j) = make_float4(
                    __uint_as_float(r[j]), __uint_as_float(r[j + 1]),
                    __uint_as_float(r[j + 2]), __uint_as_float(r[j + 3]));
            }
        }
    }
    __syncthreads();
    if (tid == 0) {
        MBARRIER_INVAL(sb + 8); MBARRIER_INVAL(sb + 16); MBARRIER_INVAL(sb + 24);
    }
    if (wid == 0) TCGEN05_DEALLOC(tmem, 256);
#endif
}

// =====================================================================
// Flash attention on tcgen05 — conservative, fixed alloc ordering.
// alloc by warp0 THEN sync THEN relinquish (no alloc/relinquish race).
// LDTM only from warps 0-3 (validated pattern). P in smem, SS-mode PV.
// Raw exp (post-LN scores bounded); O accumulates in TMEM across tiles.
// TMEM: S 0-63 | O_self 64-191 | O_cross 192-319
// CTA: (qtile=128, h, b), 256 threads.
// =====================================================================
#define AT_QH 4096
#define AT_QL (AT_QH + 32768)
#define AT_KH (AT_QL + 32768)          // 69632
#define AT_KL (AT_KH + 16384)
#define AT_VH (AT_KL + 16384)
#define AT_VL (AT_VH + 16384)
#define AT_PH (AT_VL + 16384)
#define AT_PL (AT_PH + 16384)
#define AT_SMEM (AT_PL + 16384)        // 167936

#define IDESC_S  ((1u<<4) | (1u<<7) | (1u<<10) | ((64/8)<<17)  | ((128/16)<<24))
#define IDESC_PV ((1u<<4) | (1u<<7) | (1u<<10) | ((128/8)<<17) | ((128/16)<<24))

__global__ void __launch_bounds__(256, 1) fattn_kernel(
    const float* __restrict__ Qg,
    const float* __restrict__ Kg,  const float* __restrict__ Vg,
    const float* __restrict__ YKg, const float* __restrict__ YVg,
    const float* __restrict__ gate,
    bf16* __restrict__ Oh, bf16* __restrict__ Ol)
{
#if defined(__CUDA_ARCH_FEAT_SM103_ALL) || !defined(__CUDA_ARCH__)
    extern __shared__ char smem[];
    uint32_t sb = smem_u32(smem);
    int tid = threadIdx.x, wid = tid >> 5, lane = tid & 31;
    int qt = blockIdx.x, h = blockIdx.y, b = blockIdx.z;
    int s0 = qt * 128;
    int row = wid * 32 + lane;         // for wid<4: TMEM lane / q row owned

    // ---- TMEM alloc: EXACT validated ordering (alloc -> sync -> relinq)
    if (wid == 0) TCGEN05_ALLOC(sb + 0, 512);
    if (tid == 0) { MBARRIER_INIT(sb + 8, 1); MBARRIER_INIT(sb + 16, 1); }
    __syncthreads();
    uint32_t tmem;
    asm volatile("ld.shared.b32 %0, [%1];" : "=r"(tmem) : "r"(sb + 0));
    if (wid == 0) TCGEN05_RELINQ();

    // ---- load Q tile once (fp32 -> hi/lo bf16, blocked-atom SW128) ----
    {
#pragma unroll
        for (int r = 0; r < 16; r++) {
            int e = tid + r * 256;            // 0..4095
            int qr = e >> 5;                  // 0..127
            int hc = (e & 31) * 4;            // hd chunk
            const float* src = Qg + ((size_t)(b * S_ + s0 + qr) * HHD + h * HD_ + hc);
            float4 v = *(const float4*)src;
            bf16 h0,l0,h1,l1,h2,l2,h3,l3;
            split_hl(v.x,h0,l0); split_hl(v.y,h1,l1);
            split_hl(v.z,h2,l2); split_hl(v.w,h3,l3);
            uint32_t byte = (uint32_t)((qr >> 3) * 1024 + (hc >> 6) * 16384
                                       + (qr & 7) * 128 + (hc & 63) * 2);
            uint32_t so = sw128(byte);
            uint2 hp, lp;
            hp.x = pack2(__bfloat162float(h0), __bfloat162float(h1));
            hp.y = pack2(__bfloat162float(h2), __bfloat162float(h3));
            lp.x = pack2(__bfloat162float(l0), __bfloat162float(l1));
            lp.y = pack2(__bfloat162float(l2), __bfloat162float(l3));
            *(uint2*)(smem + AT_QH + so) = hp;
            *(uint2*)(smem + AT_QL + so) = lp;
        }
    }

    float l_acc[2] = {0.f, 0.f};       // full-row sums (warps 0-3 only)
    int ps = 0, pp = 0;

    const uint64_t AOFF[8] = {0,2,4,6,1024,1026,1028,1030};
    const uint64_t BOFF[8] = {0,2,4,6,512,514,516,518};

    for (int pass = 0; pass < 2; pass++) {
        const float* Kp = pass ? YKg : Kg;
        const float* Vp = pass ? YVg : Vg;
        int Sk = pass ? LY_ : S_;
        int ntile = Sk / 64;
        uint32_t ocol = pass ? 192u : 64u;

        for (int t = 0; t < ntile; t++) {
            int key0 = t * 64;
            // ---- load K tile (64 keys x 128 hd), hi/lo, blocked SW128 ----
#pragma unroll
            for (int r = 0; r < 8; r++) {
                int e = tid + r * 256;
                int key = e >> 5;
                int hc = (e & 31) * 4;
                const float* src = Kp + ((size_t)(b * Sk + key0 + key) * HHD + h * HD_ + hc);
                float4 v = *(const float4*)src;
                bf16 h0,l0,h1,l1,h2,l2,h3,l3;
                split_hl(v.x,h0,l0); split_hl(v.y,h1,l1);
                split_hl(v.z,h2,l2); split_hl(v.w,h3,l3);
                uint32_t byte = (uint32_t)((key >> 3) * 1024 + (hc >> 6) * 8192
                                           + (key & 7) * 128 + (hc & 63) * 2);
                uint32_t so = sw128(byte);
                uint2 hp, lp;
                hp.x = pack2(__bfloat162float(h0), __bfloat162float(h1));
                hp.y = pack2(__bfloat162float(h2), __bfloat162float(h3));
                lp.x = pack2(__bfloat162float(l0), __bfloat162float(l1));
                lp.y = pack2(__bfloat162float(l2), __bfloat162float(l3));
                *(uint2*)(smem + AT_KH + so) = hp;
                *(uint2*)(smem + AT_KL + so) = lp;
            }
            // ---- load V tile transposed: VT[hd 128][key 64], hi/lo ----
#pragma unroll
            for (int r = 0; r < 4; r++) {
                int e = tid + r * 256;        // 0..1023
                int kp2 = e >> 5;             // key pair 0..31
                int hc = (e & 31) * 4;
                const float* s0p = Vp + ((size_t)(b * Sk + key0 + 2 * kp2) * HHD + h * HD_ + hc);
                float4 va = *(const float4*)s0p;
                float4 vb = *(const float4*)(s0p + HHD);
                float aa[4] = {va.x, va.y, va.z, va.w};
                float bb[4] = {vb.x, vb.y, vb.z, vb.w};
#pragma unroll
                for (int j = 0; j < 4; j++) {
                    bf16 ha, la, hb, lb;
                    split_hl(aa[j], ha, la);
                    split_hl(bb[j], hb, lb);
                    uint32_t byte = (uint32_t)((hc + j) * 128 + kp2 * 4);
                    uint32_t so = sw128(byte);
                    *(uint32_t*)(smem + AT_VH + so) =
                        pack2(__bfloat162float(ha), __bfloat162float(hb));
                    *(uint32_t*)(smem + AT_VL + so) =
                        pack2(__bfloat162float(la), __bfloat162float(lb));
                }
            }
            __syncthreads();

            // ---- S = Q K^T (3 hi/lo terms), reset each tile ----
            if (wid == 0) {
                FENCE_ASYNC_SHARED();
                TCGEN05_FENCE_AFTER();
                if (elect_one()) {
                    uint64_t qh = make_desc_sw128(sb + AT_QH);
                    uint64_t ql = make_desc_sw128(sb + AT_QL);
                    uint64_t kh = make_desc_sw128(sb + AT_KH);
                    uint64_t kl = make_desc_sw128(sb + AT_KL);
#pragma unroll
                    for (int j = 0; j < 8; j++)
                        mma_bf16_ss(tmem + 0, qh + AOFF[j], kh + BOFF[j], IDESC_S, j > 0);
#pragma unroll
                    for (int j = 0; j < 8; j++)
                        mma_bf16_ss(tmem + 0, ql + AOFF[j], kh + BOFF[j], IDESC_S, 1u);
#pragma unroll
                    for (int j = 0; j < 8; j++)
                        mma_bf16_ss(tmem + 0, qh + AOFF[j], kl + BOFF[j], IDESC_S, 1u);
                    TCGEN05_COMMIT(sb + 8);
                }
            }
            mbar_wait_parity(sb + 8, ps); ps ^= 1;
            TCGEN05_FENCE_AFTER();

            // ---- warps 0-3: read S (64 cols), exp, write P hi/lo to smem ----
            if (wid < 4) {
#pragma unroll
                for (int c = 0; c < 2; c++) {
                    uint32_t sr[32];
                    TCGEN05_LD_X32(sr, tmem + (uint32_t)c * 32);
                    TCGEN05_WAIT_LD();
                    float lsum = 0.f;
                    uint32_t pbase = (uint32_t)(row * 128 + c * 64);
#pragma unroll
                    for (int j = 0; j < 16; j++) {
                        float p0 = __expf(__uint_as_float(sr[2 * j]));
                        float p1 = __expf(__uint_as_float(sr[2 * j + 1]));
                        lsum += p0 + p1;
                        bf16 h0, l0, h1, l1;
                        split_hl(p0, h0, l0);
                        split_hl(p1, h1, l1);
                        uint32_t so = sw128(pbase + j * 4);
                        *(uint32_t*)(smem + AT_PH + so) =
                            pack2(__bfloat162float(h0), __bfloat162float(h1));
                        *(uint32_t*)(smem + AT_PL + so) =
                            pack2(__bfloat162float(l0), __bfloat162float(l1));
                    }
                    l_acc[pass] += lsum;
                }
                TCGEN05_FENCE_BEFORE();
            }
            __syncthreads();

            // ---- O += P V (SS mode, 3 hi/lo terms) ----
            if (wid == 0) {
                FENCE_ASYNC_SHARED();
                TCGEN05_FENCE_AFTER();
                if (elect_one()) {
                    uint64_t ph = make_desc_sw128(sb + AT_PH);
                    uint64_t pl = make_desc_sw128(sb + AT_PL);
                    uint64_t vh = make_desc_sw128(sb + AT_VH);
                    uint64_t vl = make_desc_sw128(sb + AT_VL);
#pragma unroll
                    for (int j = 0; j < 4; j++)
                        mma_bf16_ss(tmem + ocol, ph + j * 2, vh + j * 2, IDESC_PV,
                                    (t > 0 || j > 0) ? 1u : 0u);
#pragma unroll
                    for (int j = 0; j < 4; j++)
                        mma_bf16_ss(tmem + ocol, pl + j * 2, vh + j * 2, IDESC_PV, 1u);
#pragma unroll
                    for (int j = 0; j < 4; j++)
                        mma_bf16_ss(tmem + ocol, ph + j * 2, vl + j * 2, IDESC_PV, 1u);
                    TCGEN05_COMMIT(sb + 16);
                }
            }
            mbar_wait_parity(sb + 16, pp); pp ^= 1;
            __syncthreads();   // safe to overwrite K/V/P next tile
        }
    }

    // ---- epilogue: warps 0-3 combine self + gate*cross, write bf16 hi/lo ----
    TCGEN05_FENCE_AFTER();
    if (wid < 4) {
        float inv0 = 1.f / l_acc[0];
        float inv1 = 1.f / l_acc[1];
        float gt = tanhf(gate[h]);
        size_t obase = (size_t)(b * S_ + s0 + row) * HHD + h * HD_;
#pragma unroll
        for (int c0 = 0; c0 < 128; c0 += 32) {
            uint32_t osr[32], ocr[32];
            TCGEN05_LD_X32(osr, tmem + 64  + c0);
            TCGEN05_WAIT_LD();
            TCGEN05_LD_X32(ocr, tmem + 192 + c0);
            TCGEN05_WAIT_LD();
#pragma unroll
            for (int j = 0; j < 32; j += 2) {
                float o0 = __uint_as_float(osr[j])     * inv0 + gt * __uint_as_float(ocr[j])     * inv1;
                float o1 = __uint_as_float(osr[j + 1]) * inv0 + gt * __uint_as_float(ocr[j + 1]) * inv1;
                bf16 h0, l0, h1, l1;
                split_hl(o0, h0, l0);
                split_hl(o1, h1, l1);
                *(uint32_t*)(Oh + obase + c0 + j) = pack2(__bfloat162float(h0), __bfloat162float(h1));
                *(uint32_t*)(Ol + obase + c0 + j) = pack2(__bfloat162float(l0), __bfloat162float(l1));
            }
        }
        TCGEN05_FENCE_BEFORE();
    }
    __syncthreads();
    if (tid == 0) { MBARRIER_INVAL(sb + 8); MBARRIER_INVAL(sb + 16); }
    if (wid == 0) TCGEN05_DEALLOC(tmem, 512);
#endif
}

// =====================================================================
// elementwise fp32 -> bf16 hi/lo split
// =====================================================================
__global__ void split_kernel(const float* __restrict__ in,
                             bf16* __restrict__ hi, bf16* __restrict__ lo,
                             int n)
{
    int i = (blockIdx.x * blockDim.x + threadIdx.x) * 4;
    if (i >= n) return;
    float4 v = *(const float4*)(in + i);
    bf16 h0, l0, h1, l1, h2, l2, h3, l3;
    split_hl(v.x, h0, l0); split_hl(v.y, h1, l1);
    split_hl(v.z, h2, l2); split_hl(v.w, h3, l3);
    uint2 hp, lp;
    ((bf16*)&hp)[0] = h0; ((bf16*)&hp)[1] = h1; ((bf16*)&hp)[2] = h2; ((bf16*)&hp)[3] = h3;
    ((bf16*)&lp)[0] = l0; ((bf16*)&lp)[1] = l1; ((bf16*)&lp)[2] = l2; ((bf16*)&lp)[3] = l3;
    *(uint2*)(hi + i) = hp;
    *(uint2*)(lo + i) = lp;
}

// =====================================================================
// 2048x2048 transpose + hi/lo split
// =====================================================================
__global__ void transpose_split_kernel(const float* __restrict__ in,
                                       bf16* __restrict__ oh,
                                       bf16* __restrict__ ol)
{
    __shared__ float t[32][33];
    int c0 = blockIdx.x * 32, r0 = blockIdx.y * 32;
    int tx = threadIdx.x, ty = threadIdx.y;
#pragma unroll
    for (int i = ty; i < 32; i += 8)
        t[i][tx] = in[(size_t)(r0 + i) * 2048 + c0 + tx];
    __syncthreads();
#pragma unroll
    for (int i = ty; i < 32; i += 8) {
        float x = t[tx][i];
        bf16 h, l;
        split_hl(x, h, l);
        size_t o = (size_t)(c0 + i) * 2048 + r0 + tx;
        oh[o] = h;
        ol[o] = l;
    }
}

// =====================================================================
// Fused LayerNorm (+optional RoPE, +output scale)
// =====================================================================
__global__ void ln_rope_kernel(float* __restrict__ t,
                               const float* __restrict__ w,
                               const float* __restrict__ bias,
                               const float* __restrict__ freqs,
                               int Smod, float eps, float oscale, int do_rope)
{
    __shared__ float red[32];
    int row = blockIdx.x;
    int tid = threadIdx.x;
    float* p = t + (size_t)row * HHD;
    int base = tid * 8;

    float4 a = *(const float4*)(p + base);
    float4 c = *(const float4*)(p + base + 4);
    float v[8] = {a.x, a.y, a.z, a.w, c.x, c.y, c.z, c.w};

    float s1 = 0.f, s2 = 0.f;
#pragma unroll
    for (int j = 0; j < 8; j++) { s1 += v[j]; s2 += v[j] * v[j]; }
#pragma unroll
    for (int o = 16; o > 0; o >>= 1) {
        s1 += __shfl_down_sync(0xffffffffu, s1, o);
        s2 += __shfl_down_sync(0xffffffffu, s2, o);
    }
    int wid = tid >> 5, lane = tid & 31;
    if (lane == 0) { red[wid] = s1; red[8 + wid] = s2; }
    __syncthreads();
    if (tid == 0) {
        float t1 = 0.f, t2 = 0.f;
#pragma unroll
        for (int i = 0; i < 8; i++) { t1 += red[i]; t2 += red[8 + i]; }
        red[16] = t1; red[17] = t2;
    }
    __syncthreads();
    float mean = red[16] * (1.f / HHD);
    float var  = red[17] * (1.f / HHD) - mean * mean;
    float rstd = rsqrtf(fmaxf(var, 0.f) + eps);

#pragma unroll
    for (int j = 0; j < 8; j++) {
        int g = base + j;
        v[j] = (v[j] - mean) * rstd * w[g] + bias[g];
    }

    if (do_rope) {
        int s = row % Smod;
        const float* fr = freqs + (size_t)s * (HD_ / 2) * 2;
#pragma unroll
        for (int jp = 0; jp < 4; jp++) {
            int g = base + 2 * jp;
            int pidx = (g & (HD_ - 1)) >> 1;
            float cs = fr[pidx * 2 + 0];
            float sn = fr[pidx * 2 + 1];
            float x0 = v[2 * jp], x1 = v[2 * jp + 1];
            v[2 * jp]     = x0 * cs - x1 * sn;
            v[2 * jp + 1] = x0 * sn + x1 * cs;
        }
    }
#pragma unroll
    for (int j = 0; j < 8; j++) v[j] *= oscale;

    *(float4*)(p + base)     = make_float4(v[0], v[1], v[2], v[3]);
    *(float4*)(p + base + 4) = make_float4(v[4], v[5], v[6], v[7]);
}

// =====================================================================
// launch
// =====================================================================
extern "C" void kernel_launch(void* const* d_in, const int* in_sizes, int n_in,
                              void* d_out, int out_size)
{
    const float* x     = (const float*)d_in[0];
    const float* freqs = (const float*)d_in[2];
    const float* y     = (const float*)d_in[3];
    const float* wq    = (const float*)d_in[5];
    const float* wk    = (const float*)d_in[6];
    const float* wv    = (const float*)d_in[7];
    const float* wo    = (const float*)d_in[8];
    const float* wky   = (const float*)d_in[9];
    const float* wvy   = (const float*)d_in[10];
    const float* gate  = (const float*)d_in[11];
    const float* qn_w  = (const float*)d_in[12];
    const float* qn_b  = (const float*)d_in[13];
    const float* kn_w  = (const float*)d_in[14];
    const float* kn_b  = (const float*)d_in[15];
    const float* kyn_w = (const float*)d_in[16];
    const float* kyn_b = (const float*)d_in[17];
    float* out = (float*)d_out;

    float *q, *k, *v, *yk, *yv;
    bf16 *xh, *xl, *yh, *yl, *ath, *atl;
    bf16 *wqh, *wql, *wkh, *wkl, *wvh, *wvl, *woh, *wol, *wkyh, *wkyl, *wvyh, *wvyl;
    cudaGetSymbolAddress((void**)&q,    g_q);
    cudaGetSymbolAddress((void**)&k,    g_k);
    cudaGetSymbolAddress((void**)&v,    g_v);
    cudaGetSymbolAddress((void**)&yk,   g_yk);
    cudaGetSymbolAddress((void**)&yv,   g_yv);
    cudaGetSymbolAddress((void**)&xh,   g_xh);
    cudaGetSymbolAddress((void**)&xl,   g_xl);
    cudaGetSymbolAddress((void**)&yh,   g_yh);
    cudaGetSymbolAddress((void**)&yl,   g_yl);
    cudaGetSymbolAddress((void**)&ath,  g_ath);
    cudaGetSymbolAddress((void**)&atl,  g_atl);
    cudaGetSymbolAddress((void**)&wqh,  g_wqh);  cudaGetSymbolAddress((void**)&wql,  g_wql);
    cudaGetSymbolAddress((void**)&wkh,  g_wkh);  cudaGetSymbolAddress((void**)&wkl,  g_wkl);
    cudaGetSymbolAddress((void**)&wvh,  g_wvh);  cudaGetSymbolAddress((void**)&wvl,  g_wvl);
    cudaGetSymbolAddress((void**)&woh,  g_woh);  cudaGetSymbolAddress((void**)&wol,  g_wol);
    cudaGetSymbolAddress((void**)&wkyh, g_wkyh); cudaGetSymbolAddress((void**)&wkyl, g_wkyl);
    cudaGetSymbolAddress((void**)&wvyh, g_wvyh); cudaGetSymbolAddress((void**)&wvyl, g_wvyl);

    const int Mx = B_ * S_;    // 4096
    const int My = B_ * LY_;   // 1024

    // weights: transpose + split
    dim3 tg(64, 64), tb(32, 8);
    transpose_split_kernel<<<tg, tb>>>(wq,  wqh,  wql);
    transpose_split_kernel<<<tg, tb>>>(wk,  wkh,  wkl);
    transpose_split_kernel<<<tg, tb>>>(wv,  wvh,  wvl);
    transpose_split_kernel<<<tg, tb>>>(wo,  woh,  wol);
    transpose_split_kernel<<<tg, tb>>>(wky, wkyh, wkyl);
    transpose_split_kernel<<<tg, tb>>>(wvy, wvyh, wvyl);

    // activations split
    split_kernel<<<(Mx * D_ / 4 + 255) / 256, 256>>>(x, xh, xl, Mx * D_);
    split_kernel<<<(My * DY_ / 4 + 255) / 256, 256>>>(y, yh, yl, My * DY_);

    // tcgen05 bf16x3 GEMMs
    cudaFuncSetAttribute(bf16x3_gemm_kernel,
                         cudaFuncAttributeMaxDynamicSharedMemorySize, GSMEM);
    dim3 gx(HHD / GBN, Mx / GBM);
    dim3 gy(HHD / GBN, My / GBM);
    bf16x3_gemm_kernel<<<gx, 256, GSMEM>>>(xh, xl, wqh,  wql,  q,  Mx, HHD, D_);
    bf16x3_gemm_kernel<<<gx, 256, GSMEM>>>(xh, xl, wkh,  wkl,  k,  Mx, HHD, D_);
    bf16x3_gemm_kernel<<<gx, 256, GSMEM>>>(xh, xl, wvh,  wvl,  v,  Mx, HHD, D_);
    bf16x3_gemm_kernel<<<gy, 256, GSMEM>>>(yh, yl, wkyh, wkyl, yk, My, HHD, DY_);
    bf16x3_gemm_kernel<<<gy, 256, GSMEM>>>(yh, yl, wvyh, wvyl, yv, My, HHD, DY_);

    // LayerNorm (+RoPE). Attention scale folded into q.
    const float scale = 0.08838834764831845f;
    ln_rope_kernel<<<Mx, 256>>>(q,  qn_w,  qn_b,  freqs, S_, 1e-5f, scale, 1);
    ln_rope_kernel<<<Mx, 256>>>(k,  kn_w,  kn_b,  freqs, S_, 1e-5f, 1.f,   1);
    ln_rope_kernel<<<My, 256>>>(yk, kyn_w, kyn_b, freqs, 1,  1e-6f, 1.f,   0);

    // fused tcgen05 flash attention (self + cross), writes bf16 hi/lo
    cudaFuncSetAttribute(fattn_kernel,
                         cudaFuncAttributeMaxDynamicSharedMemorySize, AT_SMEM);
    fattn_kernel<<<dim3(S_ / 128, H_, B_), 256, AT_SMEM>>>(
        q, k, v, yk, yv, gate, ath, atl);

    // output projection
    bf16x3_gemm_kernel<<<dim3(D_ / GBN, Mx / GBM), 256, GSMEM>>>(
        ath, atl, woh, wol, out, Mx, D_, HHD);
}

// round 8
// speedup vs baseline: 5.6316x; 1.3272x over previous
#include <cuda_runtime.h>
#include <cuda_bf16.h>
#include <cuda_fp16.h>
#include <math.h>
#include <stdint.h>

#define B_   2
#define S_   2048
#define D_   2048
#define H_   16
#define HD_  128
#define LY_  512
#define DY_  2048
#define HHD  2048   // H*HD

typedef __nv_bfloat16 bf16;
typedef __half fp16;

// ---------------- scratch (no allocations allowed) ----------------
__device__ float g_q  [B_*S_*HHD];
__device__ float g_k  [B_*S_*HHD];
__device__ float g_v  [B_*S_*HHD];
__device__ float g_yk [B_*LY_*HHD];
__device__ float g_yv [B_*LY_*HHD];
// bf16 hi/lo splits
__device__ bf16 g_xh [B_*S_*D_],   g_xl [B_*S_*D_];
__device__ bf16 g_yh [B_*LY_*DY_], g_yl [B_*LY_*DY_];
__device__ bf16 g_ath[B_*S_*HHD],  g_atl[B_*S_*HHD];
__device__ bf16 g_qh [B_*S_*HHD],  g_ql [B_*S_*HHD];
__device__ bf16 g_kh [B_*S_*HHD],  g_kl [B_*S_*HHD];
__device__ bf16 g_ykh[B_*LY_*HHD], g_ykl[B_*LY_*HHD];
// fp16 hi/lo transposed V: [b][h][hd][s]
__device__ fp16 g_vth [B_*H_*HD_*S_],  g_vtl [B_*H_*HD_*S_];
__device__ fp16 g_yvth[B_*H_*HD_*LY_], g_yvtl[B_*H_*HD_*LY_];
// transposed + hi/lo split weights [N][K] bf16
__device__ bf16 g_wqh [HHD*D_],  g_wql [HHD*D_];
__device__ bf16 g_wkh [HHD*D_],  g_wkl [HHD*D_];
__device__ bf16 g_wvh [HHD*D_],  g_wvl [HHD*D_];
__device__ bf16 g_woh [D_*HHD],  g_wol [D_*HHD];
__device__ bf16 g_wkyh[HHD*DY_], g_wkyl[HHD*DY_];
__device__ bf16 g_wvyh[HHD*DY_], g_wvyl[HHD*DY_];

// =====================================================================
// Generic helpers
// =====================================================================
__device__ __forceinline__ uint32_t smem_u32(const void* p) {
    uint32_t a;
    asm("{ .reg .u64 t; cvta.to.shared.u64 t, %1; cvt.u32.u64 %0, t; }"
        : "=r"(a) : "l"(p));
    return a;
}
#define MBARRIER_INIT(addr, cnt) \
    asm volatile("mbarrier.init.shared.b64 [%0], %1;" :: "r"(addr), "r"(cnt) : "memory")
#define MBARRIER_INVAL(addr) \
    asm volatile("mbarrier.inval.shared.b64 [%0];" :: "r"(addr) : "memory")

__device__ __forceinline__ void mbar_wait_parity(uint32_t mbar, uint32_t parity) {
    asm volatile(
        "{\n\t.reg .pred P1;\n\t"
        "WAIT_LOOP_%=:\n\t"
        "mbarrier.try_wait.parity.acquire.cta.shared::cta.b64 P1, [%0], %1, 0x989680;\n\t"
        "@P1 bra.uni WAIT_DONE_%=;\n\t"
        "bra.uni WAIT_LOOP_%=;\n\t"
        "WAIT_DONE_%=:\n\t}"
        :: "r"(mbar), "r"(parity) : "memory");
}

__device__ __forceinline__ uint32_t sw128(uint32_t off) {
    return off ^ ((off >> 3) & 0x70);
}

__device__ __forceinline__ void split_hl(float x, bf16& h, bf16& l) {
    h = __float2bfloat16_rn(x);
    l = __float2bfloat16_rn(x - __bfloat162float(h));
}
__device__ __forceinline__ void split_hl16(float x, fp16& h, fp16& l) {
    h = __float2half_rn(x);
    l = __float2half_rn(x - __half2float(h));
}

__device__ __forceinline__ uint32_t pack2(float lo, float hi) {
    __nv_bfloat162 t = __floats2bfloat162_rn(lo, hi);
    return *(uint32_t*)&t;
}

// =====================================================================
// tcgen05 helpers — arch-specific pass only
// =====================================================================
#if defined(__CUDA_ARCH_FEAT_SM103_ALL) || !defined(__CUDA_ARCH__)

__device__ __forceinline__ uint32_t elect_one() {
    uint32_t pred;
    asm volatile("{\n\t.reg .pred p;\n\telect.sync _|p, 0xFFFFFFFF;\n\t"
                 "selp.b32 %0, 1, 0, p;\n\t}" : "=r"(pred));
    return pred;
}
#define TCGEN05_ALLOC(smem_addr, ncols) \
    asm volatile("tcgen05.alloc.cta_group::1.sync.aligned.shared::cta.b32 [%0], %1;" \
                 :: "r"(smem_addr), "r"(ncols) : "memory")
#define TCGEN05_DEALLOC(tmem, ncols) \
    asm volatile("tcgen05.dealloc.cta_group::1.sync.aligned.b32 %0, %1;" :: "r"(tmem), "r"(ncols))
#define TCGEN05_RELINQ() \
    asm volatile("tcgen05.relinquish_alloc_permit.cta_group::1.sync.aligned;")
#define TCGEN05_COMMIT(mbar) \
    asm volatile("tcgen05.commit.cta_group::1.mbarrier::arrive::one.shared::cluster.b64 [%0];" \
                 :: "r"(mbar) : "memory")
#define TCGEN05_WAIT_LD() asm volatile("tcgen05.wait::ld.sync.aligned;" ::: "memory")
#define TCGEN05_FENCE_BEFORE() asm volatile("tcgen05.fence::before_thread_sync;" ::: "memory")
#define TCGEN05_FENCE_AFTER()  asm volatile("tcgen05.fence::after_thread_sync;" ::: "memory")
#define FENCE_ASYNC_SHARED() asm volatile("fence.proxy.async.shared::cta;" ::: "memory")

#define TCGEN05_LD_X32(r, tmem_addr) \
    asm volatile( \
        "tcgen05.ld.sync.aligned.32x32b.x32.b32 " \
        "{%0, %1, %2, %3, %4, %5, %6, %7, " \
        " %8, %9, %10, %11, %12, %13, %14, %15, " \
        " %16, %17, %18, %19, %20, %21, %22, %23, " \
        " %24, %25, %26, %27, %28, %29, %30, %31}, [%32];" \
        : "=r"((r)[0]),  "=r"((r)[1]),  "=r"((r)[2]),  "=r"((r)[3]), \
          "=r"((r)[4]),  "=r"((r)[5]),  "=r"((r)[6]),  "=r"((r)[7]), \
          "=r"((r)[8]),  "=r"((r)[9]),  "=r"((r)[10]), "=r"((r)[11]), \
          "=r"((r)[12]), "=r"((r)[13]), "=r"((r)[14]), "=r"((r)[15]), \
          "=r"((r)[16]), "=r"((r)[17]), "=r"((r)[18]), "=r"((r)[19]), \
          "=r"((r)[20]), "=r"((r)[21]), "=r"((r)[22]), "=r"((r)[23]), \
          "=r"((r)[24]), "=r"((r)[25]), "=r"((r)[26]), "=r"((r)[27]), \
          "=r"((r)[28]), "=r"((r)[29]), "=r"((r)[30]), "=r"((r)[31]) \
        : "r"(tmem_addr))

// SW128 K-major smem descriptor: layout=SW128(2), version=1, SBO=64, LBO=1
__device__ __forceinline__ uint64_t make_desc_sw128(uint32_t addr) {
    uint64_t d = (uint64_t(2) << 61) | (uint64_t(1) << 46)
               | (uint64_t(64) << 32) | (uint64_t(1) << 16);
    return d | ((uint64_t)(addr >> 4) & 0x3FFF);
}

// f16-kind SS MMA (bf16 or fp16 per idesc)
__device__ __forceinline__ void mma_f16_ss(uint32_t d_tmem, uint64_t a_desc,
                                           uint64_t b_desc, uint32_t idesc,
                                           uint32_t enable) {
    asm volatile(
        "{\n\t.reg .pred p;\n\tsetp.ne.u32 p, %5, 0;\n\t"
        "tcgen05.mma.cta_group::1.kind::f16 [%0], %1, %2, %3, {%4, %4, %4, %4}, p;\n\t}"
        :: "r"(d_tmem), "l"(a_desc), "l"(b_desc), "r"(idesc), "r"(0u), "r"(enable)
        : "memory");
}
#endif

// =====================================================================
// bf16x3 GEMM (validated): C = (Ah+Al) @ (Bh+Bl)^T
// =====================================================================
#define GBM 128
#define GBN 256
#define GBK 64
#define STG_STRIDE 98304
#define OFF_AH 0
#define OFF_AL 16384
#define OFF_BH 32768
#define OFF_BL 65536
#define GSMEM (1024 + 2*STG_STRIDE)

#define BF16_IDESC ((1u<<4) | (1u<<7) | (1u<<10) | ((GBN/8)<<17) | ((GBM/16)<<24))

__global__ void __launch_bounds__(256, 1) bf16x3_gemm_kernel(
    const bf16* __restrict__ Ah, const bf16* __restrict__ Al,
    const bf16* __restrict__ Bh, const bf16* __restrict__ Bl,
    float* __restrict__ C, int M, int N, int K)
{
#if defined(__CUDA_ARCH_FEAT_SM103_ALL) || !defined(__CUDA_ARCH__)
    extern __shared__ char smem[];
    uint32_t sb = smem_u32(smem);
    int tid = threadIdx.x, wid = tid >> 5, lane = tid & 31;
    int bm0 = blockIdx.y * GBM, bn0 = blockIdx.x * GBN;

    if (wid == 0) TCGEN05_ALLOC(sb + 0, 256);
    if (tid == 0) {
        MBARRIER_INIT(sb + 8, 1);
        MBARRIER_INIT(sb + 16, 1);
        MBARRIER_INIT(sb + 24, 1);
    }
    __syncthreads();
    uint32_t tmem;
    asm volatile("ld.shared.b32 %0, [%1];" : "=r"(tmem) : "r"(sb + 0));
    if (wid == 0) TCGEN05_RELINQ();

    int ph0 = 0, ph1 = 0;
    const int niter = K / GBK;

    for (int i = 0; i < niter; i++) {
        int s = i & 1;
        uint32_t stg = 1024 + s * STG_STRIDE;
        if (i >= 2) {
            if (s == 0) { mbar_wait_parity(sb + 8,  ph0); ph0 ^= 1; }
            else        { mbar_wait_parity(sb + 16, ph1); ph1 ^= 1; }
        }
        int k0 = i * GBK;
        {
#pragma unroll
            for (int r = 0; r < 4; r++) {
                int e = tid + r * 256;
                int row = e >> 3;
                int ch = e & 7;
                size_t goff = (size_t)(bm0 + row) * K + k0 + ch * 8;
                uint32_t soff = sw128((uint32_t)(row * 128 + ch * 16));
                *(uint4*)(smem + stg + OFF_AH + soff) = *(const uint4*)(Ah + goff);
                *(uint4*)(smem + stg + OFF_AL + soff) = *(const uint4*)(Al + goff);
            }
        }
        {
#pragma unroll
            for (int r = 0; r < 8; r++) {
                int e = tid + r * 256;
                int row = e >> 3;
                int ch = e & 7;
                size_t goff = (size_t)(bn0 + row) * K + k0 + ch * 8;
                uint32_t soff = sw128((uint32_t)(row * 128 + ch * 16));
                *(uint4*)(smem + stg + OFF_BH + soff) = *(const uint4*)(Bh + goff);
                *(uint4*)(smem + stg + OFF_BL + soff) = *(const uint4*)(Bl + goff);
            }
        }
        __syncthreads();

        if (wid == 0) {
            FENCE_ASYNC_SHARED();
            if (elect_one()) {
                uint64_t ah = make_desc_sw128(sb + stg + OFF_AH);
                uint64_t al = make_desc_sw128(sb + stg + OFF_AL);
                uint64_t bh = make_desc_sw128(sb + stg + OFF_BH);
                uint64_t bl = make_desc_sw128(sb + stg + OFF_BL);
#pragma unroll
                for (int j = 0; j < 4; j++)
                    mma_f16_ss(tmem, ah + j * 2, bh + j * 2, BF16_IDESC,
                               (i > 0 || j > 0) ? 1u : 0u);
#pragma unroll
                for (int j = 0; j < 4; j++)
                    mma_f16_ss(tmem, ah + j * 2, bl + j * 2, BF16_IDESC, 1u);
#pragma unroll
                for (int j = 0; j < 4; j++)
                    mma_f16_ss(tmem, al + j * 2, bh + j * 2, BF16_IDESC, 1u);
                TCGEN05_COMMIT(sb + 8 + 8 * s);
            }
        }
    }

    __syncthreads();
    if (wid == 0 && elect_one()) TCGEN05_COMMIT(sb + 24);
    mbar_wait_parity(sb + 24, 0);
    TCGEN05_FENCE_AFTER();

    if (wid < 4) {
        float* crow = C + (size_t)(bm0 + wid * 32 + lane) * N + bn0;
#pragma unroll
        for (int c0 = 0; c0 < GBN; c0 += 32) {
            uint32_t r[32];
            TCGEN05_LD_X32(r, tmem + c0);
            TCGEN05_WAIT_LD();
#pragma unroll
            for (int j = 0; j < 32; j += 4) {
                *(float4*)(crow + c0 + j) = make_float4(
                    __uint_as_float(r[j]), __uint_as_float(r[j + 1]),
                    __uint_as_float(r[j + 2]), __uint_as_float(r[j + 3]));
            }
        }
    }
    __syncthreads();
    if (tid == 0) {
        MBARRIER_INVAL(sb + 8); MBARRIER_INVAL(sb + 16); MBARRIER_INVAL(sb + 24);
    }
    if (wid == 0) TCGEN05_DEALLOC(tmem, 256);
#endif
}

// =====================================================================
// Flash attention v2: pipelined, bf16 pre-split K / fp16 pre-split V^T
// inputs, fp16 P (single term) + fp16 V hi/lo (2-term PV).
// exp uses constant shift C=6 (cancels in normalization).
// TMEM: S 0-63 | O_self 64-191 | O_cross 192-319
// smem: Qh 32K | Ql 32K | 2 stages x (KH 16K|KL 16K|VH 16K|VL 16K) | P 16K
// =====================================================================
#define AT_QH 1024
#define AT_QL (AT_QH + 32768)
#define AT_STG0 (AT_QL + 32768)       // 66560
#define AT_SSTRIDE 65536
#define SO_KH 0
#define SO_KL 16384
#define SO_VH 32768
#define SO_VL 49152
#define AT_P  (AT_STG0 + 2*AT_SSTRIDE) // 197632
#define AT_SMEM (AT_P + 16384)         // 214016

#define IDESC_S    ((1u<<4) | (1u<<7) | (1u<<10) | ((64/8)<<17)  | ((128/16)<<24))
#define IDESC_PV16 ((1u<<4) | (0u<<7) | (0u<<10) | ((128/8)<<17) | ((128/16)<<24))
#define EXP_SHIFT 6.0f

__global__ void __launch_bounds__(256, 1) fattn_kernel(
    const bf16* __restrict__ Qh_g, const bf16* __restrict__ Ql_g,
    const bf16* __restrict__ Kh_g, const bf16* __restrict__ Kl_g,
    const fp16* __restrict__ VTh_g, const fp16* __restrict__ VTl_g,
    const bf16* __restrict__ YKh_g, const bf16* __restrict__ YKl_g,
    const fp16* __restrict__ YVTh_g, const fp16* __restrict__ YVTl_g,
    const float* __restrict__ gate,
    bf16* __restrict__ Oh, bf16* __restrict__ Ol)
{
#if defined(__CUDA_ARCH_FEAT_SM103_ALL) || !defined(__CUDA_ARCH__)
    extern __shared__ char smem[];
    uint32_t sb = smem_u32(smem);
    int tid = threadIdx.x, wid = tid >> 5, lane = tid & 31;
    int qt = blockIdx.x, h = blockIdx.y, b = blockIdx.z;
    int s0 = qt * 128;
    int row = wid * 32 + lane;         // for wid<4

    if (wid == 0) TCGEN05_ALLOC(sb + 0, 512);
    if (tid == 0) { MBARRIER_INIT(sb + 8, 1); MBARRIER_INIT(sb + 16, 1); }
    __syncthreads();
    uint32_t tmem;
    asm volatile("ld.shared.b32 %0, [%1];" : "=r"(tmem) : "r"(sb + 0));
    if (wid == 0) TCGEN05_RELINQ();

    // ---- load Q tile once (bf16 hi/lo copies, blocked-atom SW128) ----
    {
#pragma unroll
        for (int r = 0; r < 8; r++) {
            int e = tid + r * 256;            // 0..2047 chunks of 16B
            int qr = e >> 4;                  // 0..127
            int ch = e & 15;
            size_t goff = (size_t)(b * S_ + s0 + qr) * HHD + h * HD_ + ch * 8;
            uint32_t byte = (uint32_t)((qr >> 3) * 1024 + (ch >> 3) * 16384
                                       + (qr & 7) * 128 + (ch & 7) * 16);
            uint32_t so = sw128(byte);
            *(uint4*)(smem + AT_QH + so) = *(const uint4*)(Qh_g + goff);
            *(uint4*)(smem + AT_QL + so) = *(const uint4*)(Ql_g + goff);
        }
    }

    float l_acc[2] = {0.f, 0.f};
    int ps = 0, pp = 0;
    bool pv_pending = false;

    const uint64_t AOFF[8] = {0,2,4,6,1024,1026,1028,1030};
    const uint64_t BOFF[8] = {0,2,4,6,512,514,516,518};
    uint64_t qdh = make_desc_sw128(sb + AT_QH);
    uint64_t qdl = make_desc_sw128(sb + AT_QL);

    for (int pass = 0; pass < 2; pass++) {
        const bf16* Kph = pass ? YKh_g : Kh_g;
        const bf16* Kpl = pass ? YKl_g : Kl_g;
        const fp16* Vph = pass ? YVTh_g : VTh_g;
        const fp16* Vpl = pass ? YVTl_g : VTl_g;
        int Sk = pass ? LY_ : S_;
        int ntile = Sk / 64;
        uint32_t ocol = pass ? 192u : 64u;
        size_t vbase = ((size_t)(b * H_ + h)) * HD_ * Sk;

        // flush pending PV before reusing stage 0
        if (pv_pending) { mbar_wait_parity(sb + 16, pp); pp ^= 1; pv_pending = false; }

        // ---- preamble: load tile 0 into stage 0, issue S(0) ----
        {
            uint32_t stg = AT_STG0;
#pragma unroll
            for (int r = 0; r < 4; r++) {
                int e = tid + r * 256;        // K: 1024 chunks of 16B
                int key = e >> 4;
                int ch = e & 15;
                size_t goff = (size_t)(b * Sk + key) * HHD + h * HD_ + ch * 8;
                uint32_t byte = (uint32_t)((key >> 3) * 1024 + (ch >> 3) * 8192
                                           + (key & 7) * 128 + (ch & 7) * 16);
                uint32_t so = sw128(byte);
                *(uint4*)(smem + stg + SO_KH + so) = *(const uint4*)(Kph + goff);
                *(uint4*)(smem + stg + SO_KL + so) = *(const uint4*)(Kpl + goff);
            }
#pragma unroll
            for (int r = 0; r < 4; r++) {
                int e = tid + r * 256;        // V: 1024 chunks of 16B
                int hd = e >> 3;
                int kc = e & 7;
                size_t goff = vbase + (size_t)hd * Sk + kc * 8;
                uint32_t so = sw128((uint32_t)(hd * 128 + kc * 16));
                *(uint4*)(smem + stg + SO_VH + so) = *(const uint4*)(Vph + goff);
                *(uint4*)(smem + stg + SO_VL + so) = *(const uint4*)(Vpl + goff);
            }
        }
        __syncthreads();
        if (wid == 0) {
            FENCE_ASYNC_SHARED();
            if (elect_one()) {
                uint64_t kh = make_desc_sw128(sb + AT_STG0 + SO_KH);
                uint64_t kl = make_desc_sw128(sb + AT_STG0 + SO_KL);
#pragma unroll
                for (int j = 0; j < 8; j++)
                    mma_f16_ss(tmem, qdh + AOFF[j], kh + BOFF[j], IDESC_S, j > 0);
#pragma unroll
                for (int j = 0; j < 8; j++)
                    mma_f16_ss(tmem, qdl + AOFF[j], kh + BOFF[j], IDESC_S, 1u);
#pragma unroll
                for (int j = 0; j < 8; j++)
                    mma_f16_ss(tmem, qdh + AOFF[j], kl + BOFF[j], IDESC_S, 1u);
                TCGEN05_COMMIT(sb + 8);
            }
        }

        for (int t = 0; t < ntile; t++) {
            // free V stage (t+1)&1: PV(t-1) must be done
            if (t >= 1) { mbar_wait_parity(sb + 16, pp); pp ^= 1; }

            // load tile t+1 (overlaps S(t) execution)
            if (t + 1 < ntile) {
                uint32_t stg = AT_STG0 + (uint32_t)((t + 1) & 1) * AT_SSTRIDE;
                int key0 = (t + 1) * 64;
#pragma unroll
                for (int r = 0; r < 4; r++) {
                    int e = tid + r * 256;
                    int key = e >> 4;
                    int ch = e & 15;
                    size_t goff = (size_t)(b * Sk + key0 + key) * HHD + h * HD_ + ch * 8;
                    uint32_t byte = (uint32_t)((key >> 3) * 1024 + (ch >> 3) * 8192
                                               + (key & 7) * 128 + (ch & 7) * 16);
                    uint32_t so = sw128(byte);
                    *(uint4*)(smem + stg + SO_KH + so) = *(const uint4*)(Kph + goff);
                    *(uint4*)(smem + stg + SO_KL + so) = *(const uint4*)(Kpl + goff);
                }
#pragma unroll
                for (int r = 0; r < 4; r++) {
                    int e = tid + r * 256;
                    int hd = e >> 3;
                    int kc = e & 7;
                    size_t goff = vbase + (size_t)hd * Sk + key0 + kc * 8;
                    uint32_t so = sw128((uint32_t)(hd * 128 + kc * 16));
                    *(uint4*)(smem + stg + SO_VH + so) = *(const uint4*)(Vph + goff);
                    *(uint4*)(smem + stg + SO_VL + so) = *(const uint4*)(Vpl + goff);
                }
            }

            // wait S(t)
            mbar_wait_parity(sb + 8, ps); ps ^= 1;
            TCGEN05_FENCE_AFTER();

            // softmax: warps 0-3, full row each, fp16 P with constant shift
            if (wid < 4) {
                uint32_t pbase = (uint32_t)(row * 128);
#pragma unroll
                for (int c = 0; c < 2; c++) {
                    uint32_t sr[32];
                    TCGEN05_LD_X32(sr, tmem + (uint32_t)c * 32);
                    TCGEN05_WAIT_LD();
                    float lsum = 0.f;
#pragma unroll
                    for (int j = 0; j < 16; j++) {
                        float p0 = __expf(__uint_as_float(sr[2 * j])     - EXP_SHIFT);
                        float p1 = __expf(__uint_as_float(sr[2 * j + 1]) - EXP_SHIFT);
                        lsum += p0 + p1;
                        __half2 ph2 = __floats2half2_rn(p0, p1);
                        uint32_t so = sw128(pbase + c * 64 + j * 4);
                        *(uint32_t*)(smem + AT_P + so) = *(uint32_t*)&ph2;
                    }
                    l_acc[pass] += lsum;
                }
                TCGEN05_FENCE_BEFORE();
            }
            __syncthreads();

            // issue PV(t) then S(t+1)
            if (wid == 0) {
                FENCE_ASYNC_SHARED();
                TCGEN05_FENCE_AFTER();
                if (elect_one()) {
                    uint32_t stg = AT_STG0 + (uint32_t)(t & 1) * AT_SSTRIDE;
                    uint64_t pd = make_desc_sw128(sb + AT_P);
                    uint64_t vh = make_desc_sw128(sb + stg + SO_VH);
                    uint64_t vl = make_desc_sw128(sb + stg + SO_VL);
#pragma unroll
                    for (int j = 0; j < 4; j++)
                        mma_f16_ss(tmem + ocol, pd + j * 2, vh + j * 2, IDESC_PV16,
                                   (t > 0 || j > 0) ? 1u : 0u);
#pragma unroll
                    for (int j = 0; j < 4; j++)
                        mma_f16_ss(tmem + ocol, pd + j * 2, vl + j * 2, IDESC_PV16, 1u);
                    TCGEN05_COMMIT(sb + 16);

                    if (t + 1 < ntile) {
                        uint32_t stg2 = AT_STG0 + (uint32_t)((t + 1) & 1) * AT_SSTRIDE;
                        uint64_t kh = make_desc_sw128(sb + stg2 + SO_KH);
                        uint64_t kl = make_desc_sw128(sb + stg2 + SO_KL);
#pragma unroll
                        for (int j = 0; j < 8; j++)
                            mma_f16_ss(tmem, qdh + AOFF[j], kh + BOFF[j], IDESC_S, j > 0);
#pragma unroll
                        for (int j = 0; j < 8; j++)
                            mma_f16_ss(tmem, qdl + AOFF[j], kh + BOFF[j], IDESC_S, 1u);
#pragma unroll
                        for (int j = 0; j < 8; j++)
                            mma_f16_ss(tmem, qdh + AOFF[j], kl + BOFF[j], IDESC_S, 1u);
                        TCGEN05_COMMIT(sb + 8);
                    }
                }
            }
            pv_pending = true;
            __syncthreads();   // P buffer reuse safety handled by pv wait next iter
        }
    }

    // final flush
    if (pv_pending) { mbar_wait_parity(sb + 16, pp); pp ^= 1; }
    TCGEN05_FENCE_AFTER();

    // ---- epilogue: warps 0-3 combine self + gate*cross, write bf16 hi/lo ----
    if (wid < 4) {
        float inv0 = 1.f / l_acc[0];
        float inv1 = 1.f / l_acc[1];
        float gt = tanhf(gate[h]);
        size_t obase = (size_t)(b * S_ + s0 + row) * HHD + h * HD_;
#pragma unroll
        for (int c0 = 0; c0 < 128; c0 += 32) {
            uint32_t osr[32], ocr[32];
            TCGEN05_LD_X32(osr, tmem + 64  + c0);
            TCGEN05_WAIT_LD();
            TCGEN05_LD_X32(ocr, tmem + 192 + c0);
            TCGEN05_WAIT_LD();
#pragma unroll
            for (int j = 0; j < 32; j += 2) {
                float o0 = __uint_as_float(osr[j])     * inv0 + gt * __uint_as_float(ocr[j])     * inv1;
                float o1 = __uint_as_float(osr[j + 1]) * inv0 + gt * __uint_as_float(ocr[j + 1]) * inv1;
                bf16 h0, l0, h1, l1;
                split_hl(o0, h0, l0);
                split_hl(o1, h1, l1);
                *(uint32_t*)(Oh + obase + c0 + j) = pack2(__bfloat162float(h0), __bfloat162float(h1));
                *(uint32_t*)(Ol + obase + c0 + j) = pack2(__bfloat162float(l0), __bfloat162float(l1));
            }
        }
        TCGEN05_FENCE_BEFORE();
    }
    __syncthreads();
    if (tid == 0) { MBARRIER_INVAL(sb + 8); MBARRIER_INVAL(sb + 16); }
    if (wid == 0) TCGEN05_DEALLOC(tmem, 512);
#endif
}

// =====================================================================
// elementwise fp32 -> bf16 hi/lo split
// =====================================================================
__global__ void split_kernel(const float* __restrict__ in,
                             bf16* __restrict__ hi, bf16* __restrict__ lo,
                             int n)
{
    int i = (blockIdx.x * blockDim.x + threadIdx.x) * 4;
    if (i >= n) return;
    float4 v = *(const float4*)(in + i);
    bf16 h0, l0, h1, l1, h2, l2, h3, l3;
    split_hl(v.x, h0, l0); split_hl(v.y, h1, l1);
    split_hl(v.z, h2, l2); split_hl(v.w, h3, l3);
    uint2 hp, lp;
    ((bf16*)&hp)[0] = h0; ((bf16*)&hp)[1] = h1; ((bf16*)&hp)[2] = h2; ((bf16*)&hp)[3] = h3;
    ((bf16*)&lp)[0] = l0; ((bf16*)&lp)[1] = l1; ((bf16*)&lp)[2] = l2; ((bf16*)&lp)[3] = l3;
    *(uint2*)(hi + i) = hp;
    *(uint2*)(lo + i) = lp;
}

// =====================================================================
// V transpose + fp16 hi/lo split: v[b][s][h*HD+hd] -> vt[b][h][hd][s]
// grid (Sk/32, HD/32, B*H), block (32,8)
// =====================================================================
__global__ void vtrans_split_kernel(const float* __restrict__ in,
                                    fp16* __restrict__ oh, fp16* __restrict__ ol,
                                    int Sk)
{
    __shared__ float t[32][33];
    int s0 = blockIdx.x * 32, d0 = blockIdx.y * 32;
    int bh = blockIdx.z;
    int b = bh / H_, h = bh % H_;
    int tx = threadIdx.x, ty = threadIdx.y;
#pragma unroll
    for (int i = ty; i < 32; i += 8)
        t[i][tx] = in[((size_t)(b * Sk + s0 + i)) * HHD + h * HD_ + d0 + tx];
    __syncthreads();
#pragma unroll
    for (int i = ty; i < 32; i += 8) {
        float x = t[tx][i];
        fp16 hh, ll;
        split_hl16(x, hh, ll);
        size_t o = ((size_t)bh * HD_ + d0 + i) * Sk + s0 + tx;
        oh[o] = hh;
        ol[o] = ll;
    }
}

// =====================================================================
// 2048x2048 transpose + bf16 hi/lo split (weights)
// =====================================================================
__global__ void transpose_split_kernel(const float* __restrict__ in,
                                       bf16* __restrict__ oh,
                                       bf16* __restrict__ ol)
{
    __shared__ float t[32][33];
    int c0 = blockIdx.x * 32, r0 = blockIdx.y * 32;
    int tx = threadIdx.x, ty = threadIdx.y;
#pragma unroll
    for (int i = ty; i < 32; i += 8)
        t[i][tx] = in[(size_t)(r0 + i) * 2048 + c0 + tx];
    __syncthreads();
#pragma unroll
    for (int i = ty; i < 32; i += 8) {
        float x = t[tx][i];
        bf16 h, l;
        split_hl(x, h, l);
        size_t o = (size_t)(c0 + i) * 2048 + r0 + tx;
        oh[o] = h;
        ol[o] = l;
    }
}

// =====================================================================
// Fused LayerNorm (+optional RoPE, +scale) -> bf16 hi/lo outputs
// =====================================================================
__global__ void ln_rope_split_kernel(const float* __restrict__ in,
                                     const float* __restrict__ w,
                                     const float* __restrict__ bias,
                                     const float* __restrict__ freqs,
                                     int Smod, float eps, float oscale, int do_rope,
                                     bf16* __restrict__ oh, bf16* __restrict__ ol)
{
    __shared__ float red[32];
    int row = blockIdx.x;
    int tid = threadIdx.x;
    const float* p = in + (size_t)row * HHD;
    int base = tid * 8;

    float4 a = *(const float4*)(p + base);
    float4 c = *(const float4*)(p + base + 4);
    float v[8] = {a.x, a.y, a.z, a.w, c.x, c.y, c.z, c.w};

    float s1 = 0.f, s2 = 0.f;
#pragma unroll
    for (int j = 0; j < 8; j++) { s1 += v[j]; s2 += v[j] * v[j]; }
#pragma unroll
    for (int o = 16; o > 0; o >>= 1) {
        s1 += __shfl_down_sync(0xffffffffu, s1, o);
        s2 += __shfl_down_sync(0xffffffffu, s2, o);
    }
    int wid = tid >> 5, lane = tid & 31;
    if (lane == 0) { red[wid] = s1; red[8 + wid] = s2; }
    __syncthreads();
    if (tid == 0) {
        float t1 = 0.f, t2 = 0.f;
#pragma unroll
        for (int i = 0; i < 8; i++) { t1 += red[i]; t2 += red[8 + i]; }
        red[16] = t1; red[17] = t2;
    }
    __syncthreads();
    float mean = red[16] * (1.f / HHD);
    float var  = red[17] * (1.f / HHD) - mean * mean;
    float rstd = rsqrtf(fmaxf(var, 0.f) + eps);

#pragma unroll
    for (int j = 0; j < 8; j++) {
        int g = base + j;
        v[j] = (v[j] - mean) * rstd * w[g] + bias[g];
    }

    if (do_rope) {
        int s = row % Smod;
        const float* fr = freqs + (size_t)s * (HD_ / 2) * 2;
#pragma unroll
        for (int jp = 0; jp < 4; jp++) {
            int g = base + 2 * jp;
            int pidx = (g & (HD_ - 1)) >> 1;
            float cs = fr[pidx * 2 + 0];
            float sn = fr[pidx * 2 + 1];
            float x0 = v[2 * jp], x1 = v[2 * jp + 1];
            v[2 * jp]     = x0 * cs - x1 * sn;
            v[2 * jp + 1] = x0 * sn + x1 * cs;
        }
    }

    uint2 hp, lp;
#pragma unroll
    for (int j = 0; j < 8; j++) {
        float x = v[j] * oscale;
        bf16 hh, ll;
        split_hl(x, hh, ll);
        ((bf16*)&hp)[j & 3] = hh;
        ((bf16*)&lp)[j & 3] = ll;
        if ((j & 3) == 3) {
            *(uint2*)(oh + (size_t)row * HHD + base + j - 3) = hp;
            *(uint2*)(ol + (size_t)row * HHD + base + j - 3) = lp;
        }
    }
}

// =====================================================================
// launch
// =====================================================================
extern "C" void kernel_launch(void* const* d_in, const int* in_sizes, int n_in,
                              void* d_out, int out_size)
{
    const float* x     = (const float*)d_in[0];
    const float* freqs = (const float*)d_in[2];
    const float* y     = (const float*)d_in[3];
    const float* wq    = (const float*)d_in[5];
    const float* wk    = (const float*)d_in[6];
    const float* wv    = (const float*)d_in[7];
    const float* wo    = (const float*)d_in[8];
    const float* wky   = (const float*)d_in[9];
    const float* wvy   = (const float*)d_in[10];
    const float* gate  = (const float*)d_in[11];
    const float* qn_w  = (const float*)d_in[12];
    const float* qn_b  = (const float*)d_in[13];
    const float* kn_w  = (const float*)d_in[14];
    const float* kn_b  = (const float*)d_in[15];
    const float* kyn_w = (const float*)d_in[16];
    const float* kyn_b = (const float*)d_in[17];
    float* out = (float*)d_out;

    float *q, *k, *v, *yk, *yv;
    bf16 *xh, *xl, *yh, *yl, *ath, *atl, *qh, *ql, *kh, *kl, *ykh, *ykl;
    fp16 *vth, *vtl, *yvth, *yvtl;
    bf16 *wqh, *wql, *wkh, *wkl, *wvh, *wvl, *woh, *wol, *wkyh, *wkyl, *wvyh, *wvyl;
    cudaGetSymbolAddress((void**)&q,    g_q);
    cudaGetSymbolAddress((void**)&k,    g_k);
    cudaGetSymbolAddress((void**)&v,    g_v);
    cudaGetSymbolAddress((void**)&yk,   g_yk);
    cudaGetSymbolAddress((void**)&yv,   g_yv);
    cudaGetSymbolAddress((void**)&xh,   g_xh);
    cudaGetSymbolAddress((void**)&xl,   g_xl);
    cudaGetSymbolAddress((void**)&yh,   g_yh);
    cudaGetSymbolAddress((void**)&yl,   g_yl);
    cudaGetSymbolAddress((void**)&ath,  g_ath);
    cudaGetSymbolAddress((void**)&atl,  g_atl);
    cudaGetSymbolAddress((void**)&qh,   g_qh);
    cudaGetSymbolAddress((void**)&ql,   g_ql);
    cudaGetSymbolAddress((void**)&kh,   g_kh);
    cudaGetSymbolAddress((void**)&kl,   g_kl);
    cudaGetSymbolAddress((void**)&ykh,  g_ykh);
    cudaGetSymbolAddress((void**)&ykl,  g_ykl);
    cudaGetSymbolAddress((void**)&vth,  g_vth);
    cudaGetSymbolAddress((void**)&vtl,  g_vtl);
    cudaGetSymbolAddress((void**)&yvth, g_yvth);
    cudaGetSymbolAddress((void**)&yvtl, g_yvtl);
    cudaGetSymbolAddress((void**)&wqh,  g_wqh);  cudaGetSymbolAddress((void**)&wql,  g_wql);
    cudaGetSymbolAddress((void**)&wkh,  g_wkh);  cudaGetSymbolAddress((void**)&wkl,  g_wkl);
    cudaGetSymbolAddress((void**)&wvh,  g_wvh);  cudaGetSymbolAddress((void**)&wvl,  g_wvl);
    cudaGetSymbolAddress((void**)&woh,  g_woh);  cudaGetSymbolAddress((void**)&wol,  g_wol);
    cudaGetSymbolAddress((void**)&wkyh, g_wkyh); cudaGetSymbolAddress((void**)&wkyl, g_wkyl);
    cudaGetSymbolAddress((void**)&wvyh, g_wvyh); cudaGetSymbolAddress((void**)&wvyl, g_wvyl);

    const int Mx = B_ * S_;    // 4096
    const int My = B_ * LY_;   // 1024

    // weights: transpose + split
    dim3 tg(64, 64), tb(32, 8);
    transpose_split_kernel<<<tg, tb>>>(wq,  wqh,  wql);
    transpose_split_kernel<<<tg, tb>>>(wk,  wkh,  wkl);
    transpose_split_kernel<<<tg, tb>>>(wv,  wvh,  wvl);
    transpose_split_kernel<<<tg, tb>>>(wo,  woh,  wol);
    transpose_split_kernel<<<tg, tb>>>(wky, wkyh, wkyl);
    transpose_split_kernel<<<tg, tb>>>(wvy, wvyh, wvyl);

    // activations split
    split_kernel<<<(Mx * D_ / 4 + 255) / 256, 256>>>(x, xh, xl, Mx * D_);
    split_kernel<<<(My * DY_ / 4 + 255) / 256, 256>>>(y, yh, yl, My * DY_);

    // tcgen05 bf16x3 GEMMs
    cudaFuncSetAttribute(bf16x3_gemm_kernel,
                         cudaFuncAttributeMaxDynamicSharedMemorySize, GSMEM);
    dim3 gx(HHD / GBN, Mx / GBM);
    dim3 gy(HHD / GBN, My / GBM);
    bf16x3_gemm_kernel<<<gx, 256, GSMEM>>>(xh, xl, wqh,  wql,  q,  Mx, HHD, D_);
    bf16x3_gemm_kernel<<<gx, 256, GSMEM>>>(xh, xl, wkh,  wkl,  k,  Mx, HHD, D_);
    bf16x3_gemm_kernel<<<gx, 256, GSMEM>>>(xh, xl, wvh,  wvl,  v,  Mx, HHD, D_);
    bf16x3_gemm_kernel<<<gy, 256, GSMEM>>>(yh, yl, wkyh, wkyl, yk, My, HHD, DY_);
    bf16x3_gemm_kernel<<<gy, 256, GSMEM>>>(yh, yl, wvyh, wvyl, yv, My, HHD, DY_);

    // LayerNorm (+RoPE) -> bf16 hi/lo. Attention scale folded into q.
    const float scale = 0.08838834764831845f;
    ln_rope_split_kernel<<<Mx, 256>>>(q,  qn_w,  qn_b,  freqs, S_, 1e-5f, scale, 1, qh,  ql);
    ln_rope_split_kernel<<<Mx, 256>>>(k,  kn_w,  kn_b,  freqs, S_, 1e-5f, 1.f,   1, kh,  kl);
    ln_rope_split_kernel<<<My, 256>>>(yk, kyn_w, kyn_b, freqs, 1,  1e-6f, 1.f,   0, ykh, ykl);

    // V: transpose + fp16 hi/lo split
    vtrans_split_kernel<<<dim3(S_ / 32, HD_ / 32, B_ * H_), dim3(32, 8)>>>(v,  vth,  vtl,  S_);
    vtrans_split_kernel<<<dim3(LY_ / 32, HD_ / 32, B_ * H_), dim3(32, 8)>>>(yv, yvth, yvtl, LY_);

    // fused pipelined tcgen05 flash attention
    cudaFuncSetAttribute(fattn_kernel,
                         cudaFuncAttributeMaxDynamicSharedMemorySize, AT_SMEM);
    fattn_kernel<<<dim3(S_ / 128, H_, B_), 256, AT_SMEM>>>(
        qh, ql, kh, kl, vth, vtl, ykh, ykl, yvth, yvtl, gate, ath, atl);

    // output projection
    bf16x3_gemm_kernel<<<dim3(D_ / GBN, Mx / GBM), 256, GSMEM>>>(
        ath, atl, woh, wol, out, Mx, D_, HHD);
}